// round 11
// baseline (speedup 1.0000x reference)
#include <cuda_runtime.h>
#include <cuda_bf16.h>
#include <cstdint>
#include <math.h>

#define BSZ 4096
#define TT  24
#define HID 1024
#define H3  3072
#define SEC 1040          // one K-section: 1024 h + 1 dec + 12 aux + 1 bias + 2 pad
#define KB3 3136          // 3*SEC = 3120 padded to multiple of 64
#define CHUNKS 49         // KB3 / 64
#define STAGES 3
#define GRU_WARPS 8
#define GEMM_GRID 256     // persistent: 3 tiles per CTA (768 total)
#define NT_TILES 24       // H3/128

// ---------------- device globals (no cudaMalloc anywhere) ----------------
__device__ __nv_bfloat16 g_Abf[(size_t)BSZ * KB3];  // [A_hi | A_lo | A_hi] per row
__device__ __nv_bfloat16 g_Wbf[(size_t)H3 * KB3];   // [W_hi | W_hi | W_lo] per row
__device__ float g_gates[(size_t)BSZ * H3];         // GEMM out: [r | z | h_n]
__device__ float g_H[(size_t)BSZ * HID];            // fp32 hidden state
__device__ float g_inaux[(size_t)TT * BSZ * HID];   // aux-part of i_n, all steps
__device__ float g_loss;

__device__ __forceinline__ float tanh_fast(float x) {
    float y;
    asm("tanh.approx.f32 %0, %1;" : "=f"(y) : "f"(x));
    return y;
}
__device__ __forceinline__ float sigmoid_fast(float x) {
    return 0.5f * tanh_fast(0.5f * x) + 0.5f;
}

__device__ __forceinline__ void split_bf(float x, __nv_bfloat16& hi, __nv_bfloat16& lo) {
    hi = __float2bfloat16(x);
    lo = __float2bfloat16(x - __bfloat162float(hi));
}

// ---------------- PTX helpers (compute_100-safe only) ----------------
__device__ __forceinline__ uint32_t smem_u32(const void* p) {
    uint32_t a;
    asm("{ .reg .u64 t; cvta.to.shared.u64 t, %1; cvt.u32.u64 %0, t; }" : "=r"(a) : "l"(p));
    return a;
}
__device__ __forceinline__ void cp_async16(uint32_t dst, const void* src) {
    asm volatile("cp.async.cg.shared.global [%0], [%1], 16;\n" :: "r"(dst), "l"(src));
}
__device__ __forceinline__ void cp_commit() { asm volatile("cp.async.commit_group;\n"); }
template <int N> __device__ __forceinline__ void cp_waitg() {
    asm volatile("cp.async.wait_group %0;\n" :: "n"(N));
}
__device__ __forceinline__ void ldm_x4(uint32_t& r0, uint32_t& r1, uint32_t& r2, uint32_t& r3,
                                       uint32_t addr) {
    asm volatile("ldmatrix.sync.aligned.m8n8.x4.shared.b16 {%0,%1,%2,%3}, [%4];"
                 : "=r"(r0), "=r"(r1), "=r"(r2), "=r"(r3) : "r"(addr));
}
__device__ __forceinline__ void mma_bf16(float& c0, float& c1, float& c2, float& c3,
                                         uint32_t a0, uint32_t a1, uint32_t a2, uint32_t a3,
                                         uint32_t b0, uint32_t b1) {
    asm volatile("mma.sync.aligned.m16n8k16.row.col.f32.bf16.bf16.f32 "
                 "{%0,%1,%2,%3}, {%4,%5,%6,%7}, {%8,%9}, {%0,%1,%2,%3};"
                 : "+f"(c0), "+f"(c1), "+f"(c2), "+f"(c3)
                 : "r"(a0), "r"(a1), "r"(a2), "r"(a3), "r"(b0), "r"(b1));
}
__device__ __forceinline__ uint32_t sw128(uint32_t bo) { return bo ^ ((bo >> 3) & 0x70); }

// ---------------------------------------------------------------------------
// Init: A" <- split(hn), g_H <- hn, pads <- 0, t=0 x-columns, loss <- 0
// ---------------------------------------------------------------------------
__global__ void k_init(const float* __restrict__ hn, const float* __restrict__ cur_pm,
                       const float* __restrict__ aux) {
    int row = blockIdx.x;
    int tid = threadIdx.x;
    __nv_bfloat16* Ab = g_Abf + (size_t)row * KB3;
    for (int j = tid; j < HID; j += blockDim.x) {
        float x = hn[row * HID + j];
        __nv_bfloat16 hi, lo;
        split_bf(x, hi, lo);
        Ab[j] = hi; Ab[SEC + j] = lo; Ab[2 * SEC + j] = hi;
        g_H[row * HID + j] = x;
    }
    if (tid < 16) Ab[3120 + tid] = __float2bfloat16(0.0f);
    if (tid < 14) {
        float xv = (tid == 0) ? cur_pm[row]
                 : (tid == 13) ? 1.0f
                 : aux[(row * TT + 0) * 12 + (tid - 1)];
        __nv_bfloat16 hi, lo;
        split_bf(xv, hi, lo);
        Ab[1024 + tid] = hi;
        Ab[SEC + 1024 + tid] = lo;
        Ab[2 * SEC + 1024 + tid] = hi;
    }
    if (tid == 0) {
        __nv_bfloat16 z = __float2bfloat16(0.0f);
        for (int s = 0; s < 3; s++) { Ab[s * SEC + 1038] = z; Ab[s * SEC + 1039] = z; }
        if (row == 0) g_loss = 0.0f;
    }
}

// ---------------------------------------------------------------------------
// Build W" bf16 [3072 x 3136]: sections [W_hi | W_hi | W_lo]
// ---------------------------------------------------------------------------
__global__ void k_wbf(const float* __restrict__ W_hh, const float* __restrict__ W_ih,
                      const float* __restrict__ b_ih, const float* __restrict__ b_hh) {
    size_t total = (size_t)H3 * KB3;
    for (size_t idx = (size_t)blockIdx.x * blockDim.x + threadIdx.x; idx < total;
         idx += (size_t)gridDim.x * blockDim.x) {
        int c = (int)(idx / KB3);
        int k = (int)(idx - (size_t)c * KB3);
        __nv_bfloat16 outv;
        if (k >= 3120) {
            outv = __float2bfloat16(0.0f);
        } else {
            int sec = k / SEC;
            int kk = k - sec * SEC;
            float val;
            if (kk < 1024) val = W_hh[c * 1024 + kk];
            else if (kk <= 1036) val = (c < 2048) ? W_ih[c * 13 + (kk - 1024)] : 0.0f;
            else if (kk == 1037) val = (c < 2048) ? (b_ih[c] + b_hh[c]) : b_hh[c];
            else val = 0.0f;
            __nv_bfloat16 hi, lo;
            split_bf(val, hi, lo);
            outv = (sec < 2) ? hi : lo;
        }
        g_Wbf[idx] = outv;
    }
}

// ---------------------------------------------------------------------------
// Precompute aux-part of i_n for ALL steps (fp32):
//   g_inaux[t][row][j] = b_ih[2048+j] + sum_f aux[row,t,f] * W_ih[(2048+j)*13 + 1 + f]
// ---------------------------------------------------------------------------
__global__ void __launch_bounds__(256) k_inaux(const float* __restrict__ aux,
                                               const float* __restrict__ W_ih,
                                               const float* __restrict__ b_ih) {
    extern __shared__ float wt[];  // wt[c*1024 + j]
    int tid = threadIdx.x;
    for (int idx = tid; idx < 13 * HID; idx += 256) {
        int c = idx >> 10, j = idx & 1023;
        wt[idx] = (c == 0) ? b_ih[2048 + j] : W_ih[(2048 + j) * 13 + c];
    }
    __syncthreads();
    int t = blockIdx.x;
    int lane = tid & 31, wid = tid >> 5;
    for (int rr = 0; rr < 8; rr++) {
        int row = blockIdx.y * 64 + wid * 8 + rr;
        float ax[12];
#pragma unroll
        for (int f = 0; f < 12; f++) ax[f] = aux[(row * TT + t) * 12 + f];
        float* out = g_inaux + ((size_t)t * BSZ + row) * HID;
#pragma unroll 2
        for (int j = lane; j < HID; j += 32) {
            float s = wt[j];
#pragma unroll
            for (int f = 0; f < 12; f++) s = fmaf(ax[f], wt[(f + 1) * HID + j], s);
            out[j] = s;
        }
    }
}

// ---------------------------------------------------------------------------
// Persistent tensor-core GEMM: gates[m][n] = sum_k A"[m][k] * W"[n][k]
// 256 CTAs x 3 tiles (128x128 each). Flattened 147-step chunk loop keeps the
// 3-stage cp.async pipeline primed across tile boundaries. Fragment
// double-buffering skews ldmatrix one kk ahead of the MMA stream.
// ---------------------------------------------------------------------------
__global__ void __launch_bounds__(256, 2) k_gemm_mma() {
    extern __shared__ char smem[];
    uint32_t sb = smem_u32(smem);
    const int tid = threadIdx.x;
    const int wid = tid >> 5;
    const int lane = tid & 31;
    const int bid = blockIdx.x;
    const int wm = wid >> 2;          // 0..1 -> 64-row slab
    const int wn = wid & 3;           // 0..3 -> 32-col slab

    float acc[4][4][4];
#pragma unroll
    for (int i = 0; i < 4; i++)
#pragma unroll
        for (int j = 0; j < 4; j++)
#pragma unroll
            for (int v2 = 0; v2 < 4; v2++) acc[i][j][v2] = 0.0f;

    const int rA = (lane & 7) + ((lane >> 3) & 1) * 8;
    const int cA = (lane >> 4) * 16;
    const int rB = lane & 7;
    const int hB = ((lane >> 3) & 1) * 16;
    const int pB = (lane >> 4);

    // FILL stage s with chunk c of tile (prefetch-time recomputed pointers)
#define FILL(s, Ag, Wg, c) do {                                                  \
    uint32_t _ab = sb + (uint32_t)(s) * 32768u;                                  \
    uint32_t _bb = _ab + 16384u;                                                 \
    _Pragma("unroll")                                                            \
    for (int q = 0; q < 4; q++) {                                                \
        int i = tid + q * 256;                                                   \
        int row = i >> 3, seg = i & 7;                                           \
        uint32_t bo = (uint32_t)(row * 128 + seg * 16);                          \
        uint32_t sw = sw128(bo);                                                 \
        const char* ga = (const char*)((Ag) + (size_t)row * KB3 + (c) * 64) + seg * 16; \
        const char* gb = (const char*)((Wg) + (size_t)row * KB3 + (c) * 64) + seg * 16; \
        cp_async16(_ab + sw, ga);                                                \
        cp_async16(_bb + sw, gb);                                                \
    }                                                                            \
} while (0)

#define TILE_PTRS(pt, Ag, Wg) \
    int _id = bid + GEMM_GRID * (pt);                                            \
    const __nv_bfloat16* Ag = g_Abf + (size_t)(_id / NT_TILES) * 128 * KB3;      \
    const __nv_bfloat16* Wg = g_Wbf + (size_t)(_id % NT_TILES) * 128 * KB3;

    {
        TILE_PTRS(0, Ag0, Wg0);
        FILL(0, Ag0, Wg0, 0); cp_commit();
        FILL(1, Ag0, Wg0, 1); cp_commit();
    }

    const int TOT = 3 * CHUNKS;  // 147
    for (int step = 0; step < TOT; step++) {
        int tau = step / CHUNKS;
        int c = step - tau * CHUNKS;
        int pn = step + 2;
        // waitg: this step's chunk complete (groups retire in order); the single
        // barrier publishes it AND certifies stage (step+2)%3 is reusable.
        if (pn < TOT) {
            cp_waitg<1>();
            __syncthreads();
            int pt = pn / CHUNKS;
            int pc = pn - pt * CHUNKS;
            TILE_PTRS(pt, Agp, Wgp);
            FILL(pn % 3, Agp, Wgp, pc);
            cp_commit();
        } else if (step + 1 < TOT) {
            cp_waitg<1>();
            __syncthreads();
        } else {
            cp_waitg<0>();
            __syncthreads();
        }

        uint32_t ab = sb + (uint32_t)(step % 3) * 32768u;
        uint32_t bb = ab + 16384u;

        uint32_t af[2][4][4];
        uint32_t bfr[2][4][2];

#define LOADF(buf, kk) do {                                                      \
    _Pragma("unroll")                                                            \
    for (int mt = 0; mt < 4; mt++) {                                             \
        uint32_t bo = (uint32_t)((wm * 64 + mt * 16 + rA) * 128 + (kk) * 32 + cA); \
        ldm_x4(af[buf][mt][0], af[buf][mt][1], af[buf][mt][2], af[buf][mt][3],   \
               ab + sw128(bo));                                                  \
    }                                                                            \
    _Pragma("unroll")                                                            \
    for (int ntp = 0; ntp < 2; ntp++) {                                          \
        uint32_t bo = (uint32_t)((wn * 32 + (ntp * 2 + pB) * 8 + rB) * 128 + (kk) * 32 + hB); \
        ldm_x4(bfr[buf][ntp * 2][0], bfr[buf][ntp * 2][1],                       \
               bfr[buf][ntp * 2 + 1][0], bfr[buf][ntp * 2 + 1][1],               \
               bb + sw128(bo));                                                  \
    }                                                                            \
} while (0)

#define MMAS(buf) do {                                                           \
    _Pragma("unroll")                                                            \
    for (int mt = 0; mt < 4; mt++)                                               \
        _Pragma("unroll")                                                        \
        for (int nt = 0; nt < 4; nt++)                                           \
            mma_bf16(acc[mt][nt][0], acc[mt][nt][1], acc[mt][nt][2], acc[mt][nt][3], \
                     af[buf][mt][0], af[buf][mt][1], af[buf][mt][2], af[buf][mt][3], \
                     bfr[buf][nt][0], bfr[buf][nt][1]);                          \
} while (0)

        LOADF(0, 0);
        LOADF(1, 1);
        MMAS(0);
        LOADF(0, 2);
        MMAS(1);
        LOADF(1, 3);
        MMAS(0);
        MMAS(1);

#undef LOADF
#undef MMAS

        if (c == CHUNKS - 1) {
            // epilogue for tile tau (register-only; no barrier needed)
            int id = bid + GEMM_GRID * tau;
            int bm = (id / NT_TILES) * 128;
            int bn = (id % NT_TILES) * 128;
            int quad = lane >> 2;
            int tig = lane & 3;
#pragma unroll
            for (int mt = 0; mt < 4; mt++) {
                int row0 = bm + wm * 64 + mt * 16 + quad;
#pragma unroll
                for (int nt = 0; nt < 4; nt++) {
                    int col = bn + wn * 32 + nt * 8 + tig * 2;
                    *(float2*)&g_gates[(size_t)row0 * H3 + col] =
                        make_float2(acc[mt][nt][0], acc[mt][nt][1]);
                    *(float2*)&g_gates[(size_t)(row0 + 8) * H3 + col] =
                        make_float2(acc[mt][nt][2], acc[mt][nt][3]);
                    acc[mt][nt][0] = 0.0f; acc[mt][nt][1] = 0.0f;
                    acc[mt][nt][2] = 0.0f; acc[mt][nt][3] = 0.0f;
                }
            }
        }
    }
#undef FILL
#undef TILE_PTRS
}

// ---------------------------------------------------------------------------
// Warp-per-row GRU elementwise + reductions + fused x-fill for step t+1.
// i_n = g_inaux[t][row] + dec * w1.  smem = w1 (4KB) + ew (24KB) -> 28KB.
// ---------------------------------------------------------------------------
__global__ void __launch_bounds__(256) k_gru_w(
    const float* __restrict__ W_ih, const float* __restrict__ emb,
    const float* __restrict__ W_out, const float* __restrict__ b_out,
    const int* __restrict__ st, const float* __restrict__ aux,
    const float* __restrict__ tgt_seq, const float* __restrict__ v,
    float* __restrict__ outp, int t)
{
    extern __shared__ float sh[];
    float* w1 = sh;            // [1024]: W_ih[(2048+j)*13 + 0]  (dec column)
    float* ew = sh + HID;      // j*6: [emb0..emb4 | W_out]
    __shared__ float sloss;
    int tid = threadIdx.x;

    for (int j = tid; j < HID; j += 256) w1[j] = W_ih[(2048 + j) * 13];
    for (int idx = tid; idx < HID * 6; idx += 256) {
        int j = idx / 6, c = idx - j * 6;
        ew[idx] = (c < 5) ? emb[c * HID + j] : W_out[j];
    }
    if (tid == 0) sloss = 0.0f;
    __syncthreads();

    int lane = tid & 31;
    int wid = tid >> 5;
    int row = blockIdx.x * GRU_WARPS + wid;

    const float* gr = g_gates + (size_t)row * H3;
    const float* inx = g_inaux + ((size_t)t * BSZ + row) * HID;
    __nv_bfloat16* Ab = g_Abf + (size_t)row * KB3;
    float* Hrow = g_H + (size_t)row * HID;

    float dec = __bfloat162float(Ab[1024]) + __bfloat162float(Ab[SEC + 1024]);

    float e0 = 0.f, e1 = 0.f, e2 = 0.f, e3 = 0.f, e4 = 0.f, od = 0.f;

#pragma unroll 4
    for (int j = lane; j < HID; j += 32) {
        float r = sigmoid_fast(gr[j]);
        float z = sigmoid_fast(gr[1024 + j]);
        float in_ = fmaf(dec, w1[j], inx[j]);
        float n = tanh_fast(fmaf(r, gr[2048 + j], in_));
        float hp = Hrow[j];
        float h = (1.0f - z) * n + z * hp;
        Hrow[j] = h;
        __nv_bfloat16 hi, lo;
        split_bf(h, hi, lo);
        Ab[j] = hi; Ab[SEC + j] = lo; Ab[2 * SEC + j] = hi;
        const float* e = &ew[j * 6];
        e0 = fmaf(h, e[0], e0);
        e1 = fmaf(h, e[1], e1);
        e2 = fmaf(h, e[2], e2);
        e3 = fmaf(h, e[3], e3);
        e4 = fmaf(h, e[4], e4);
        od = fmaf(h, e[5], od);
    }

    float vals[6] = {e0, e1, e2, e3, e4, od};
#pragma unroll
    for (int s = 16; s > 0; s >>= 1)
#pragma unroll
        for (int vv = 0; vv < 6; vv++)
            vals[vv] += __shfl_down_sync(0xffffffffu, vals[vv], s);

    float o = 0.0f;
    if (lane == 0) {
        float mx = vals[0];
#pragma unroll
        for (int k2 = 1; k2 < 5; k2++) mx = fmaxf(mx, vals[k2]);
        float se = 0.f;
#pragma unroll
        for (int k2 = 0; k2 < 5; k2++) se += __expf(vals[k2] - mx);
        float lse = mx + __logf(se);
        int pos = st[row * TT + t];
        atomicAdd(&sloss, lse - vals[pos]);
        o = vals[5] + b_out[0];
        outp[row * TT + t] = o;
    }
    o = __shfl_sync(0xffffffffu, o, 0);

    // fused x-fill for step t+1
    if (t + 1 < TT && lane < 14) {
        float xv;
        if (lane == 0) {
            float tg = tgt_seq[row * TT + t];
            float m = (tg != 0.0f) ? v[row * TT + t + 1] : 0.0f;
            xv = (m == 1.0f) ? tg : o;
        } else if (lane == 13) {
            xv = 1.0f;
        } else {
            xv = aux[(row * TT + t + 1) * 12 + (lane - 1)];
        }
        __nv_bfloat16 hi, lo;
        split_bf(xv, hi, lo);
        Ab[1024 + lane] = hi;
        Ab[SEC + 1024 + lane] = lo;
        Ab[2 * SEC + 1024 + lane] = hi;
    }

    __syncthreads();
    if (tid == 0) atomicAdd(&g_loss, sloss);
}

// ---------------------------------------------------------------------------
__global__ void k_final(float* outp, int out_size) {
    if (out_size > BSZ * TT)
        outp[BSZ * TT] = g_loss * (1.0f / ((float)BSZ * (float)TT));
}

// ---------------------------------------------------------------------------
extern "C" void kernel_launch(void* const* d_in, const int* in_sizes, int n_in,
                              void* d_out, int out_size) {
    const float* aux    = (const float*)d_in[0];
    const float* cur_pm = (const float*)d_in[1];
    const float* hn     = (const float*)d_in[2];
    const int*   st     = (const int*)  d_in[3];
    const float* tgt    = (const float*)d_in[4];
    const float* v      = (const float*)d_in[5];
    const float* W_ih   = (const float*)d_in[6];
    const float* W_hh   = (const float*)d_in[7];
    const float* b_ih   = (const float*)d_in[8];
    const float* b_hh   = (const float*)d_in[9];
    const float* emb    = (const float*)d_in[10];
    const float* W_out  = (const float*)d_in[11];
    const float* b_out  = (const float*)d_in[12];
    float* outp = (float*)d_out;

    const int gemm_smem  = STAGES * 32768;       // 96 KB -> 2 CTAs/SM
    const int gru_smem   = (HID + HID * 6) * 4;  // 28 KB
    const int inaux_smem = 13 * HID * 4;         // 52 KB
    cudaFuncSetAttribute(k_gru_w, cudaFuncAttributeMaxDynamicSharedMemorySize, gru_smem);
    cudaFuncSetAttribute(k_gemm_mma, cudaFuncAttributeMaxDynamicSharedMemorySize, gemm_smem);
    cudaFuncSetAttribute(k_inaux, cudaFuncAttributeMaxDynamicSharedMemorySize, inaux_smem);

    k_init<<<BSZ, 256>>>(hn, cur_pm, aux);
    k_wbf<<<2048, 256>>>(W_hh, W_ih, b_ih, b_hh);
    {
        dim3 gi(TT, BSZ / 64);
        k_inaux<<<gi, 256, inaux_smem>>>(aux, W_ih, b_ih);
    }

    for (int t = 0; t < TT; t++) {
        k_gemm_mma<<<GEMM_GRID, 256, gemm_smem>>>();
        k_gru_w<<<BSZ / GRU_WARPS, 256, gru_smem>>>(W_ih, emb, W_out, b_out, st,
                                                    aux, tgt, v, outp, t);
    }
    k_final<<<1, 1>>>(outp, out_size);
}

// round 12
// speedup vs baseline: 1.0684x; 1.0684x over previous
#include <cuda_runtime.h>
#include <cuda_bf16.h>
#include <cstdint>
#include <math.h>

#define BSZ 4096
#define TT  24
#define HID 1024
#define H3  3072
#define SEC 1040          // one K-section: 1024 h + 1 dec + 12 aux + 1 bias + 2 pad
#define KB3 3136          // 3*SEC = 3120 padded to multiple of 64
#define CHUNKS 49         // KB3 / 64
#define STAGES 3
#define GRU_WARPS 8

// ---------------- device globals (no cudaMalloc anywhere) ----------------
__device__ __nv_bfloat16 g_Abf[(size_t)BSZ * KB3];  // [A_hi | A_lo | A_hi] per row
__device__ __nv_bfloat16 g_Wbf[(size_t)H3 * KB3];   // [W_hi | W_hi | W_lo] per row
__device__ float g_gates[(size_t)BSZ * H3];         // GEMM out: [r | z | h_n]
__device__ float g_H[(size_t)BSZ * HID];            // fp32 hidden state
__device__ float g_inaux[(size_t)TT * BSZ * HID];   // aux-part of i_n, all steps
__device__ float g_loss;

__device__ __forceinline__ float tanh_fast(float x) {
    float y;
    asm("tanh.approx.f32 %0, %1;" : "=f"(y) : "f"(x));
    return y;
}
__device__ __forceinline__ float sigmoid_fast(float x) {
    return 0.5f * tanh_fast(0.5f * x) + 0.5f;
}

__device__ __forceinline__ void split_bf(float x, __nv_bfloat16& hi, __nv_bfloat16& lo) {
    hi = __float2bfloat16(x);
    lo = __float2bfloat16(x - __bfloat162float(hi));
}

// ---------------- PTX helpers (compute_100-safe only) ----------------
__device__ __forceinline__ uint32_t smem_u32(const void* p) {
    uint32_t a;
    asm("{ .reg .u64 t; cvta.to.shared.u64 t, %1; cvt.u32.u64 %0, t; }" : "=r"(a) : "l"(p));
    return a;
}
__device__ __forceinline__ void cp_async16(uint32_t dst, const void* src) {
    asm volatile("cp.async.cg.shared.global [%0], [%1], 16;\n" :: "r"(dst), "l"(src));
}
__device__ __forceinline__ void cp_commit() { asm volatile("cp.async.commit_group;\n"); }
template <int N> __device__ __forceinline__ void cp_waitg() {
    asm volatile("cp.async.wait_group %0;\n" :: "n"(N));
}
__device__ __forceinline__ void ldm_x4(uint32_t& r0, uint32_t& r1, uint32_t& r2, uint32_t& r3,
                                       uint32_t addr) {
    asm volatile("ldmatrix.sync.aligned.m8n8.x4.shared.b16 {%0,%1,%2,%3}, [%4];"
                 : "=r"(r0), "=r"(r1), "=r"(r2), "=r"(r3) : "r"(addr));
}
__device__ __forceinline__ void mma_bf16(float& c0, float& c1, float& c2, float& c3,
                                         uint32_t a0, uint32_t a1, uint32_t a2, uint32_t a3,
                                         uint32_t b0, uint32_t b1) {
    asm volatile("mma.sync.aligned.m16n8k16.row.col.f32.bf16.bf16.f32 "
                 "{%0,%1,%2,%3}, {%4,%5,%6,%7}, {%8,%9}, {%0,%1,%2,%3};"
                 : "+f"(c0), "+f"(c1), "+f"(c2), "+f"(c3)
                 : "r"(a0), "r"(a1), "r"(a2), "r"(a3), "r"(b0), "r"(b1));
}
__device__ __forceinline__ uint32_t sw128(uint32_t bo) { return bo ^ ((bo >> 3) & 0x70); }

// ---------------------------------------------------------------------------
// Init: A" <- split(hn), g_H <- hn, pads <- 0, t=0 x-columns, loss <- 0
// ---------------------------------------------------------------------------
__global__ void k_init(const float* __restrict__ hn, const float* __restrict__ cur_pm,
                       const float* __restrict__ aux) {
    int row = blockIdx.x;
    int tid = threadIdx.x;
    __nv_bfloat16* Ab = g_Abf + (size_t)row * KB3;
    for (int j = tid; j < HID; j += blockDim.x) {
        float x = hn[row * HID + j];
        __nv_bfloat16 hi, lo;
        split_bf(x, hi, lo);
        Ab[j] = hi; Ab[SEC + j] = lo; Ab[2 * SEC + j] = hi;
        g_H[row * HID + j] = x;
    }
    if (tid < 16) Ab[3120 + tid] = __float2bfloat16(0.0f);
    if (tid < 14) {
        float xv = (tid == 0) ? cur_pm[row]
                 : (tid == 13) ? 1.0f
                 : aux[(row * TT + 0) * 12 + (tid - 1)];
        __nv_bfloat16 hi, lo;
        split_bf(xv, hi, lo);
        Ab[1024 + tid] = hi;
        Ab[SEC + 1024 + tid] = lo;
        Ab[2 * SEC + 1024 + tid] = hi;
    }
    if (tid == 0) {
        __nv_bfloat16 z = __float2bfloat16(0.0f);
        for (int s = 0; s < 3; s++) { Ab[s * SEC + 1038] = z; Ab[s * SEC + 1039] = z; }
        if (row == 0) g_loss = 0.0f;
    }
}

// ---------------------------------------------------------------------------
// Build W" bf16 [3072 x 3136]: sections [W_hi | W_hi | W_lo]
// ---------------------------------------------------------------------------
__global__ void k_wbf(const float* __restrict__ W_hh, const float* __restrict__ W_ih,
                      const float* __restrict__ b_ih, const float* __restrict__ b_hh) {
    size_t total = (size_t)H3 * KB3;
    for (size_t idx = (size_t)blockIdx.x * blockDim.x + threadIdx.x; idx < total;
         idx += (size_t)gridDim.x * blockDim.x) {
        int c = (int)(idx / KB3);
        int k = (int)(idx - (size_t)c * KB3);
        __nv_bfloat16 outv;
        if (k >= 3120) {
            outv = __float2bfloat16(0.0f);
        } else {
            int sec = k / SEC;
            int kk = k - sec * SEC;
            float val;
            if (kk < 1024) val = W_hh[c * 1024 + kk];
            else if (kk <= 1036) val = (c < 2048) ? W_ih[c * 13 + (kk - 1024)] : 0.0f;
            else if (kk == 1037) val = (c < 2048) ? (b_ih[c] + b_hh[c]) : b_hh[c];
            else val = 0.0f;
            __nv_bfloat16 hi, lo;
            split_bf(val, hi, lo);
            outv = (sec < 2) ? hi : lo;
        }
        g_Wbf[idx] = outv;
    }
}

// ---------------------------------------------------------------------------
// Precompute aux-part of i_n for ALL steps (fp32):
//   g_inaux[t][row][j] = b_ih[2048+j] + sum_f aux[row,t,f] * W_ih[(2048+j)*13 + 1 + f]
// ---------------------------------------------------------------------------
__global__ void __launch_bounds__(256) k_inaux(const float* __restrict__ aux,
                                               const float* __restrict__ W_ih,
                                               const float* __restrict__ b_ih) {
    extern __shared__ float wt[];  // wt[c*1024 + j]
    int tid = threadIdx.x;
    for (int idx = tid; idx < 13 * HID; idx += 256) {
        int c = idx >> 10, j = idx & 1023;
        wt[idx] = (c == 0) ? b_ih[2048 + j] : W_ih[(2048 + j) * 13 + c];
    }
    __syncthreads();
    int t = blockIdx.x;
    int lane = tid & 31, wid = tid >> 5;
    for (int rr = 0; rr < 8; rr++) {
        int row = blockIdx.y * 64 + wid * 8 + rr;
        float ax[12];
#pragma unroll
        for (int f = 0; f < 12; f++) ax[f] = aux[(row * TT + t) * 12 + f];
        float* out = g_inaux + ((size_t)t * BSZ + row) * HID;
#pragma unroll 2
        for (int j = lane; j < HID; j += 32) {
            float s = wt[j];
#pragma unroll
            for (int f = 0; f < 12; f++) s = fmaf(ax[f], wt[(f + 1) * HID + j], s);
            out[j] = s;
        }
    }
}

// ---------------------------------------------------------------------------
// Tensor-core GEMM via mma.sync: gates[m][n] = sum_k A"[m][k] * W"[n][k]
// 128x128 CTA tile, grid 768, K-chunks of 64 bf16 (SW128), 3-stage cp.async
// pipeline (96KB smem -> 2 CTAs/SM), ONE __syncthreads per chunk, prefetch
// distance 2, fragment double-buffering (ldmatrix one kk ahead of MMAs).
// No div/mod in the hot loop.
// ---------------------------------------------------------------------------
__global__ void __launch_bounds__(256, 2) k_gemm_mma() {
    extern __shared__ char smem[];
    uint32_t sb = smem_u32(smem);
    const int tid = threadIdx.x;
    const int wid = tid >> 5;
    const int lane = tid & 31;
    const int bn = blockIdx.x * 128;  // 24 N-tiles
    const int bm = blockIdx.y * 128;  // 32 M-tiles
    const int wm = wid >> 2;          // 0..1 -> 64-row slab
    const int wn = wid & 3;           // 0..3 -> 32-col slab

    const __nv_bfloat16* Ag = g_Abf + (size_t)bm * KB3;
    const __nv_bfloat16* Wg = g_Wbf + (size_t)bn * KB3;

    float acc[4][4][4];
#pragma unroll
    for (int i = 0; i < 4; i++)
#pragma unroll
        for (int j = 0; j < 4; j++)
#pragma unroll
            for (int v2 = 0; v2 < 4; v2++) acc[i][j][v2] = 0.0f;

    const int rA = (lane & 7) + ((lane >> 3) & 1) * 8;
    const int cA = (lane >> 4) * 16;
    const int rB = lane & 7;
    const int hB = ((lane >> 3) & 1) * 16;
    const int pB = (lane >> 4);

#define FILL(s, c) do {                                                          \
    uint32_t _ab = sb + (uint32_t)(s) * 32768u;                                  \
    uint32_t _bb = _ab + 16384u;                                                 \
    _Pragma("unroll")                                                            \
    for (int q = 0; q < 4; q++) {                                                \
        int i = tid + q * 256;                                                   \
        int row = i >> 3, seg = i & 7;                                           \
        uint32_t bo = (uint32_t)(row * 128 + seg * 16);                          \
        uint32_t sw = sw128(bo);                                                 \
        const char* ga = (const char*)(Ag + (size_t)row * KB3 + (c) * 64) + seg * 16; \
        const char* gb = (const char*)(Wg + (size_t)row * KB3 + (c) * 64) + seg * 16; \
        cp_async16(_ab + sw, ga);                                                \
        cp_async16(_bb + sw, gb);                                                \
    }                                                                            \
} while (0)

    FILL(0, 0); cp_commit();
    FILL(1, 1); cp_commit();

    // stage rotation without %: st3 cycles 0,1,2,0,...
    int st3 = 0;      // stage of current chunk c
    int pf3 = 2;      // stage of prefetch chunk c+2

    for (int c = 0; c < CHUNKS; c++) {
        if (c + 2 < CHUNKS) {
            cp_waitg<1>();
            __syncthreads();
            FILL(pf3, c + 2);
            cp_commit();
        } else if (c + 1 < CHUNKS) {
            cp_waitg<1>();
            __syncthreads();
        } else {
            cp_waitg<0>();
            __syncthreads();
        }

        uint32_t ab = sb + (uint32_t)st3 * 32768u;
        uint32_t bb = ab + 16384u;

        uint32_t af[2][4][4];
        uint32_t bfr[2][4][2];

#define LOADF(buf, kk) do {                                                      \
    _Pragma("unroll")                                                            \
    for (int mt = 0; mt < 4; mt++) {                                             \
        uint32_t bo = (uint32_t)((wm * 64 + mt * 16 + rA) * 128 + (kk) * 32 + cA); \
        ldm_x4(af[buf][mt][0], af[buf][mt][1], af[buf][mt][2], af[buf][mt][3],   \
               ab + sw128(bo));                                                  \
    }                                                                            \
    _Pragma("unroll")                                                            \
    for (int ntp = 0; ntp < 2; ntp++) {                                          \
        uint32_t bo = (uint32_t)((wn * 32 + (ntp * 2 + pB) * 8 + rB) * 128 + (kk) * 32 + hB); \
        ldm_x4(bfr[buf][ntp * 2][0], bfr[buf][ntp * 2][1],                       \
               bfr[buf][ntp * 2 + 1][0], bfr[buf][ntp * 2 + 1][1],               \
               bb + sw128(bo));                                                  \
    }                                                                            \
} while (0)

#define MMAS(buf) do {                                                           \
    _Pragma("unroll")                                                            \
    for (int mt = 0; mt < 4; mt++)                                               \
        _Pragma("unroll")                                                        \
        for (int nt = 0; nt < 4; nt++)                                           \
            mma_bf16(acc[mt][nt][0], acc[mt][nt][1], acc[mt][nt][2], acc[mt][nt][3], \
                     af[buf][mt][0], af[buf][mt][1], af[buf][mt][2], af[buf][mt][3], \
                     bfr[buf][nt][0], bfr[buf][nt][1]);                          \
} while (0)

        LOADF(0, 0);
        LOADF(1, 1);
        MMAS(0);
        LOADF(0, 2);
        MMAS(1);
        LOADF(1, 3);
        MMAS(0);
        MMAS(1);

#undef LOADF
#undef MMAS

        st3 = (st3 == 2) ? 0 : st3 + 1;
        pf3 = (pf3 == 2) ? 0 : pf3 + 1;
    }
#undef FILL

    int quad = lane >> 2;
    int tig = lane & 3;
#pragma unroll
    for (int mt = 0; mt < 4; mt++) {
        int row0 = bm + wm * 64 + mt * 16 + quad;
#pragma unroll
        for (int nt = 0; nt < 4; nt++) {
            int col = bn + wn * 32 + nt * 8 + tig * 2;
            *(float2*)&g_gates[(size_t)row0 * H3 + col] =
                make_float2(acc[mt][nt][0], acc[mt][nt][1]);
            *(float2*)&g_gates[(size_t)(row0 + 8) * H3 + col] =
                make_float2(acc[mt][nt][2], acc[mt][nt][3]);
        }
    }
}

// ---------------------------------------------------------------------------
// Warp-per-row GRU elementwise + reductions + fused x-fill for step t+1.
// i_n = g_inaux[t][row] + dec * w1.  smem = w1 (4KB) + ew (24KB) -> 28KB.
// ---------------------------------------------------------------------------
__global__ void __launch_bounds__(256) k_gru_w(
    const float* __restrict__ W_ih, const float* __restrict__ emb,
    const float* __restrict__ W_out, const float* __restrict__ b_out,
    const int* __restrict__ st, const float* __restrict__ aux,
    const float* __restrict__ tgt_seq, const float* __restrict__ v,
    float* __restrict__ outp, int t)
{
    extern __shared__ float sh[];
    float* w1 = sh;            // [1024]: W_ih[(2048+j)*13 + 0]  (dec column)
    float* ew = sh + HID;      // j*6: [emb0..emb4 | W_out]
    __shared__ float sloss;
    int tid = threadIdx.x;

    for (int j = tid; j < HID; j += 256) w1[j] = W_ih[(2048 + j) * 13];
    for (int idx = tid; idx < HID * 6; idx += 256) {
        int j = idx / 6, c = idx - j * 6;
        ew[idx] = (c < 5) ? emb[c * HID + j] : W_out[j];
    }
    if (tid == 0) sloss = 0.0f;
    __syncthreads();

    int lane = tid & 31;
    int wid = tid >> 5;
    int row = blockIdx.x * GRU_WARPS + wid;

    const float* gr = g_gates + (size_t)row * H3;
    const float* inx = g_inaux + ((size_t)t * BSZ + row) * HID;
    __nv_bfloat16* Ab = g_Abf + (size_t)row * KB3;
    float* Hrow = g_H + (size_t)row * HID;

    float dec = __bfloat162float(Ab[1024]) + __bfloat162float(Ab[SEC + 1024]);

    float e0 = 0.f, e1 = 0.f, e2 = 0.f, e3 = 0.f, e4 = 0.f, od = 0.f;

#pragma unroll 4
    for (int j = lane; j < HID; j += 32) {
        float r = sigmoid_fast(gr[j]);
        float z = sigmoid_fast(gr[1024 + j]);
        float in_ = fmaf(dec, w1[j], inx[j]);
        float n = tanh_fast(fmaf(r, gr[2048 + j], in_));
        float hp = Hrow[j];
        float h = (1.0f - z) * n + z * hp;
        Hrow[j] = h;
        __nv_bfloat16 hi, lo;
        split_bf(h, hi, lo);
        Ab[j] = hi; Ab[SEC + j] = lo; Ab[2 * SEC + j] = hi;
        const float* e = &ew[j * 6];
        e0 = fmaf(h, e[0], e0);
        e1 = fmaf(h, e[1], e1);
        e2 = fmaf(h, e[2], e2);
        e3 = fmaf(h, e[3], e3);
        e4 = fmaf(h, e[4], e4);
        od = fmaf(h, e[5], od);
    }

    float vals[6] = {e0, e1, e2, e3, e4, od};
#pragma unroll
    for (int s = 16; s > 0; s >>= 1)
#pragma unroll
        for (int vv = 0; vv < 6; vv++)
            vals[vv] += __shfl_down_sync(0xffffffffu, vals[vv], s);

    float o = 0.0f;
    if (lane == 0) {
        float mx = vals[0];
#pragma unroll
        for (int k2 = 1; k2 < 5; k2++) mx = fmaxf(mx, vals[k2]);
        float se = 0.f;
#pragma unroll
        for (int k2 = 0; k2 < 5; k2++) se += __expf(vals[k2] - mx);
        float lse = mx + __logf(se);
        int pos = st[row * TT + t];
        atomicAdd(&sloss, lse - vals[pos]);
        o = vals[5] + b_out[0];
        outp[row * TT + t] = o;
    }
    o = __shfl_sync(0xffffffffu, o, 0);

    // fused x-fill for step t+1
    if (t + 1 < TT && lane < 14) {
        float xv;
        if (lane == 0) {
            float tg = tgt_seq[row * TT + t];
            float m = (tg != 0.0f) ? v[row * TT + t + 1] : 0.0f;
            xv = (m == 1.0f) ? tg : o;
        } else if (lane == 13) {
            xv = 1.0f;
        } else {
            xv = aux[(row * TT + t + 1) * 12 + (lane - 1)];
        }
        __nv_bfloat16 hi, lo;
        split_bf(xv, hi, lo);
        Ab[1024 + lane] = hi;
        Ab[SEC + 1024 + lane] = lo;
        Ab[2 * SEC + 1024 + lane] = hi;
    }

    __syncthreads();
    if (tid == 0) atomicAdd(&g_loss, sloss);
}

// ---------------------------------------------------------------------------
__global__ void k_final(float* outp, int out_size) {
    if (out_size > BSZ * TT)
        outp[BSZ * TT] = g_loss * (1.0f / ((float)BSZ * (float)TT));
}

// ---------------------------------------------------------------------------
extern "C" void kernel_launch(void* const* d_in, const int* in_sizes, int n_in,
                              void* d_out, int out_size) {
    const float* aux    = (const float*)d_in[0];
    const float* cur_pm = (const float*)d_in[1];
    const float* hn     = (const float*)d_in[2];
    const int*   st     = (const int*)  d_in[3];
    const float* tgt    = (const float*)d_in[4];
    const float* v      = (const float*)d_in[5];
    const float* W_ih   = (const float*)d_in[6];
    const float* W_hh   = (const float*)d_in[7];
    const float* b_ih   = (const float*)d_in[8];
    const float* b_hh   = (const float*)d_in[9];
    const float* emb    = (const float*)d_in[10];
    const float* W_out  = (const float*)d_in[11];
    const float* b_out  = (const float*)d_in[12];
    float* outp = (float*)d_out;

    const int gemm_smem  = STAGES * 32768;       // 96 KB -> 2 CTAs/SM
    const int gru_smem   = (HID + HID * 6) * 4;  // 28 KB
    const int inaux_smem = 13 * HID * 4;         // 52 KB
    cudaFuncSetAttribute(k_gru_w, cudaFuncAttributeMaxDynamicSharedMemorySize, gru_smem);
    cudaFuncSetAttribute(k_gemm_mma, cudaFuncAttributeMaxDynamicSharedMemorySize, gemm_smem);
    cudaFuncSetAttribute(k_inaux, cudaFuncAttributeMaxDynamicSharedMemorySize, inaux_smem);

    k_init<<<BSZ, 256>>>(hn, cur_pm, aux);
    k_wbf<<<2048, 256>>>(W_hh, W_ih, b_ih, b_hh);
    {
        dim3 gi(TT, BSZ / 64);
        k_inaux<<<gi, 256, inaux_smem>>>(aux, W_ih, b_ih);
    }

    dim3 gg(H3 / 128, BSZ / 128);
    for (int t = 0; t < TT; t++) {
        k_gemm_mma<<<gg, 256, gemm_smem>>>();
        k_gru_w<<<BSZ / GRU_WARPS, 256, gru_smem>>>(W_ih, emb, W_out, b_out, st,
                                                    aux, tgt, v, outp, t);
    }
    k_final<<<1, 1>>>(outp, out_size);
}

// round 13
// speedup vs baseline: 1.0825x; 1.0132x over previous
#include <cuda_runtime.h>
#include <cuda_bf16.h>
#include <cstdint>
#include <math.h>

#define BSZ 4096
#define TT  24
#define HID 1024
#define H3  3072
#define SEC 1040          // one K-section: 1024 h + 1 dec + 12 aux + 1 bias + 2 pad
#define KB3 3136          // 3*SEC = 3120 padded to multiple of 64
#define CHUNKS 49         // KB3 / 64
#define STAGES 3
#define GRU_WARPS 8

// ---------------- device globals (no cudaMalloc anywhere) ----------------
__device__ __nv_bfloat16 g_Abf[(size_t)BSZ * KB3];  // [A_hi | A_lo | A_hi] per row
__device__ __nv_bfloat16 g_Wbf[(size_t)H3 * KB3];   // [W_hi | W_hi | W_lo] per row
__device__ float g_gates[(size_t)BSZ * H3];         // GEMM out: [r | z | h_n]
__device__ float g_H[(size_t)BSZ * HID];            // fp32 hidden state
__device__ float g_inaux[(size_t)TT * BSZ * HID];   // aux-part of i_n, all steps
__device__ float g_loss;

__device__ __forceinline__ float tanh_fast(float x) {
    float y;
    asm("tanh.approx.f32 %0, %1;" : "=f"(y) : "f"(x));
    return y;
}
__device__ __forceinline__ float sigmoid_fast(float x) {
    return 0.5f * tanh_fast(0.5f * x) + 0.5f;
}

__device__ __forceinline__ void split_bf(float x, __nv_bfloat16& hi, __nv_bfloat16& lo) {
    hi = __float2bfloat16(x);
    lo = __float2bfloat16(x - __bfloat162float(hi));
}

// ---------------- PTX helpers (compute_100-safe only) ----------------
__device__ __forceinline__ uint32_t smem_u32(const void* p) {
    uint32_t a;
    asm("{ .reg .u64 t; cvta.to.shared.u64 t, %1; cvt.u32.u64 %0, t; }" : "=r"(a) : "l"(p));
    return a;
}
__device__ __forceinline__ void cp_async16(uint32_t dst, const void* src) {
    asm volatile("cp.async.cg.shared.global [%0], [%1], 16;\n" :: "r"(dst), "l"(src));
}
__device__ __forceinline__ void cp_commit() { asm volatile("cp.async.commit_group;\n"); }
template <int N> __device__ __forceinline__ void cp_waitg() {
    asm volatile("cp.async.wait_group %0;\n" :: "n"(N));
}
__device__ __forceinline__ void ldm_x4(uint32_t& r0, uint32_t& r1, uint32_t& r2, uint32_t& r3,
                                       uint32_t addr) {
    asm volatile("ldmatrix.sync.aligned.m8n8.x4.shared.b16 {%0,%1,%2,%3}, [%4];"
                 : "=r"(r0), "=r"(r1), "=r"(r2), "=r"(r3) : "r"(addr));
}
__device__ __forceinline__ void mma_bf16(float& c0, float& c1, float& c2, float& c3,
                                         uint32_t a0, uint32_t a1, uint32_t a2, uint32_t a3,
                                         uint32_t b0, uint32_t b1) {
    asm volatile("mma.sync.aligned.m16n8k16.row.col.f32.bf16.bf16.f32 "
                 "{%0,%1,%2,%3}, {%4,%5,%6,%7}, {%8,%9}, {%0,%1,%2,%3};"
                 : "+f"(c0), "+f"(c1), "+f"(c2), "+f"(c3)
                 : "r"(a0), "r"(a1), "r"(a2), "r"(a3), "r"(b0), "r"(b1));
}
__device__ __forceinline__ uint32_t sw128(uint32_t bo) { return bo ^ ((bo >> 3) & 0x70); }

// ---------------------------------------------------------------------------
// Init: A" <- split(hn), g_H <- hn, pads <- 0, t=0 x-columns, loss <- 0
// ---------------------------------------------------------------------------
__global__ void k_init(const float* __restrict__ hn, const float* __restrict__ cur_pm,
                       const float* __restrict__ aux) {
    int row = blockIdx.x;
    int tid = threadIdx.x;
    __nv_bfloat16* Ab = g_Abf + (size_t)row * KB3;
    for (int j = tid; j < HID; j += blockDim.x) {
        float x = hn[row * HID + j];
        __nv_bfloat16 hi, lo;
        split_bf(x, hi, lo);
        Ab[j] = hi; Ab[SEC + j] = lo; Ab[2 * SEC + j] = hi;
        g_H[row * HID + j] = x;
    }
    if (tid < 16) Ab[3120 + tid] = __float2bfloat16(0.0f);
    if (tid < 14) {
        float xv = (tid == 0) ? cur_pm[row]
                 : (tid == 13) ? 1.0f
                 : aux[(row * TT + 0) * 12 + (tid - 1)];
        __nv_bfloat16 hi, lo;
        split_bf(xv, hi, lo);
        Ab[1024 + tid] = hi;
        Ab[SEC + 1024 + tid] = lo;
        Ab[2 * SEC + 1024 + tid] = hi;
    }
    if (tid == 0) {
        __nv_bfloat16 z = __float2bfloat16(0.0f);
        for (int s = 0; s < 3; s++) { Ab[s * SEC + 1038] = z; Ab[s * SEC + 1039] = z; }
        if (row == 0) g_loss = 0.0f;
    }
}

// ---------------------------------------------------------------------------
// Build W" bf16 [3072 x 3136]: sections [W_hi | W_hi | W_lo]
// ---------------------------------------------------------------------------
__global__ void k_wbf(const float* __restrict__ W_hh, const float* __restrict__ W_ih,
                      const float* __restrict__ b_ih, const float* __restrict__ b_hh) {
    size_t total = (size_t)H3 * KB3;
    for (size_t idx = (size_t)blockIdx.x * blockDim.x + threadIdx.x; idx < total;
         idx += (size_t)gridDim.x * blockDim.x) {
        int c = (int)(idx / KB3);
        int k = (int)(idx - (size_t)c * KB3);
        __nv_bfloat16 outv;
        if (k >= 3120) {
            outv = __float2bfloat16(0.0f);
        } else {
            int sec = k / SEC;
            int kk = k - sec * SEC;
            float val;
            if (kk < 1024) val = W_hh[c * 1024 + kk];
            else if (kk <= 1036) val = (c < 2048) ? W_ih[c * 13 + (kk - 1024)] : 0.0f;
            else if (kk == 1037) val = (c < 2048) ? (b_ih[c] + b_hh[c]) : b_hh[c];
            else val = 0.0f;
            __nv_bfloat16 hi, lo;
            split_bf(val, hi, lo);
            outv = (sec < 2) ? hi : lo;
        }
        g_Wbf[idx] = outv;
    }
}

// ---------------------------------------------------------------------------
// Precompute aux-part of i_n for ALL steps (fp32):
//   g_inaux[t][row][j] = b_ih[2048+j] + sum_f aux[row,t,f] * W_ih[(2048+j)*13 + 1 + f]
// ---------------------------------------------------------------------------
__global__ void __launch_bounds__(256) k_inaux(const float* __restrict__ aux,
                                               const float* __restrict__ W_ih,
                                               const float* __restrict__ b_ih) {
    extern __shared__ float wt[];  // wt[c*1024 + j]
    int tid = threadIdx.x;
    for (int idx = tid; idx < 13 * HID; idx += 256) {
        int c = idx >> 10, j = idx & 1023;
        wt[idx] = (c == 0) ? b_ih[2048 + j] : W_ih[(2048 + j) * 13 + c];
    }
    __syncthreads();
    int t = blockIdx.x;
    int lane = tid & 31, wid = tid >> 5;
    for (int rr = 0; rr < 8; rr++) {
        int row = blockIdx.y * 64 + wid * 8 + rr;
        float ax[12];
#pragma unroll
        for (int f = 0; f < 12; f++) ax[f] = aux[(row * TT + t) * 12 + f];
        float* out = g_inaux + ((size_t)t * BSZ + row) * HID;
#pragma unroll 2
        for (int j = lane; j < HID; j += 32) {
            float s = wt[j];
#pragma unroll
            for (int f = 0; f < 12; f++) s = fmaf(ax[f], wt[(f + 1) * HID + j], s);
            out[j] = s;
        }
    }
}

// ---------------------------------------------------------------------------
// Tensor-core GEMM via mma.sync: gates[m][n] = sum_k A"[m][k] * W"[n][k]
// 128x128 CTA tile, block 128 (4 warps, 2x2 grid of 64x64 warp tiles).
// Bigger warp tiles cut ldmatrix crossbar traffic 1.5x vs 8x(64x32).
// 3-stage cp.async pipeline (96KB smem, 2 CTAs/SM via 256 regs/thread),
// ONE __syncthreads per chunk, prefetch distance 2, kk fragment skew.
// ---------------------------------------------------------------------------
__global__ void __launch_bounds__(128, 2) k_gemm_mma() {
    extern __shared__ char smem[];
    uint32_t sb = smem_u32(smem);
    const int tid = threadIdx.x;      // 0..127
    const int wid = tid >> 5;         // 0..3
    const int lane = tid & 31;
    const int bn = blockIdx.x * 128;  // 24 N-tiles
    const int bm = blockIdx.y * 128;  // 32 M-tiles
    const int wm = wid >> 1;          // 0..1 -> 64-row slab
    const int wn = wid & 1;           // 0..1 -> 64-col slab

    const __nv_bfloat16* Ag = g_Abf + (size_t)bm * KB3;
    const __nv_bfloat16* Wg = g_Wbf + (size_t)bn * KB3;

    float acc[4][8][4];
#pragma unroll
    for (int i = 0; i < 4; i++)
#pragma unroll
        for (int j = 0; j < 8; j++)
#pragma unroll
            for (int v2 = 0; v2 < 4; v2++) acc[i][j][v2] = 0.0f;

    const int rA = (lane & 7) + ((lane >> 3) & 1) * 8;
    const int cA = (lane >> 4) * 16;
    const int rB = lane & 7;
    const int hB = ((lane >> 3) & 1) * 16;
    const int pB = (lane >> 4);

#define FILL(s, c) do {                                                          \
    uint32_t _ab = sb + (uint32_t)(s) * 32768u;                                  \
    uint32_t _bb = _ab + 16384u;                                                 \
    _Pragma("unroll")                                                            \
    for (int q = 0; q < 8; q++) {                                                \
        int i = tid + q * 128;                                                   \
        int row = i >> 3, seg = i & 7;                                           \
        uint32_t bo = (uint32_t)(row * 128 + seg * 16);                          \
        uint32_t sw = sw128(bo);                                                 \
        const char* ga = (const char*)(Ag + (size_t)row * KB3 + (c) * 64) + seg * 16; \
        const char* gb = (const char*)(Wg + (size_t)row * KB3 + (c) * 64) + seg * 16; \
        cp_async16(_ab + sw, ga);                                                \
        cp_async16(_bb + sw, gb);                                                \
    }                                                                            \
} while (0)

    FILL(0, 0); cp_commit();
    FILL(1, 1); cp_commit();

    // stage rotation without %: st3 cycles 0,1,2,0,...
    int st3 = 0;      // stage of current chunk c
    int pf3 = 2;      // stage of prefetch chunk c+2

    for (int c = 0; c < CHUNKS; c++) {
        if (c + 2 < CHUNKS) {
            cp_waitg<1>();
            __syncthreads();
            FILL(pf3, c + 2);
            cp_commit();
        } else if (c + 1 < CHUNKS) {
            cp_waitg<1>();
            __syncthreads();
        } else {
            cp_waitg<0>();
            __syncthreads();
        }

        uint32_t ab = sb + (uint32_t)st3 * 32768u;
        uint32_t bb = ab + 16384u;

        uint32_t af[2][4][4];
        uint32_t bfr[2][8][2];

#define LOADF(buf, kk) do {                                                      \
    _Pragma("unroll")                                                            \
    for (int mt = 0; mt < 4; mt++) {                                             \
        uint32_t bo = (uint32_t)((wm * 64 + mt * 16 + rA) * 128 + (kk) * 32 + cA); \
        ldm_x4(af[buf][mt][0], af[buf][mt][1], af[buf][mt][2], af[buf][mt][3],   \
               ab + sw128(bo));                                                  \
    }                                                                            \
    _Pragma("unroll")                                                            \
    for (int ntp = 0; ntp < 4; ntp++) {                                          \
        uint32_t bo = (uint32_t)((wn * 64 + (ntp * 2 + pB) * 8 + rB) * 128 + (kk) * 32 + hB); \
        ldm_x4(bfr[buf][ntp * 2][0], bfr[buf][ntp * 2][1],                       \
               bfr[buf][ntp * 2 + 1][0], bfr[buf][ntp * 2 + 1][1],               \
               bb + sw128(bo));                                                  \
    }                                                                            \
} while (0)

#define MMAS(buf) do {                                                           \
    _Pragma("unroll")                                                            \
    for (int mt = 0; mt < 4; mt++)                                               \
        _Pragma("unroll")                                                        \
        for (int nt = 0; nt < 8; nt++)                                           \
            mma_bf16(acc[mt][nt][0], acc[mt][nt][1], acc[mt][nt][2], acc[mt][nt][3], \
                     af[buf][mt][0], af[buf][mt][1], af[buf][mt][2], af[buf][mt][3], \
                     bfr[buf][nt][0], bfr[buf][nt][1]);                          \
} while (0)

        LOADF(0, 0);
        LOADF(1, 1);
        MMAS(0);
        LOADF(0, 2);
        MMAS(1);
        LOADF(1, 3);
        MMAS(0);
        MMAS(1);

#undef LOADF
#undef MMAS

        st3 = (st3 == 2) ? 0 : st3 + 1;
        pf3 = (pf3 == 2) ? 0 : pf3 + 1;
    }
#undef FILL

    int quad = lane >> 2;
    int tig = lane & 3;
#pragma unroll
    for (int mt = 0; mt < 4; mt++) {
        int row0 = bm + wm * 64 + mt * 16 + quad;
#pragma unroll
        for (int nt = 0; nt < 8; nt++) {
            int col = bn + wn * 64 + nt * 8 + tig * 2;
            *(float2*)&g_gates[(size_t)row0 * H3 + col] =
                make_float2(acc[mt][nt][0], acc[mt][nt][1]);
            *(float2*)&g_gates[(size_t)(row0 + 8) * H3 + col] =
                make_float2(acc[mt][nt][2], acc[mt][nt][3]);
        }
    }
}

// ---------------------------------------------------------------------------
// Warp-per-row GRU elementwise + reductions + fused x-fill for step t+1.
// i_n = g_inaux[t][row] + dec * w1.  smem = w1 (4KB) + ew (24KB) -> 28KB.
// ---------------------------------------------------------------------------
__global__ void __launch_bounds__(256) k_gru_w(
    const float* __restrict__ W_ih, const float* __restrict__ emb,
    const float* __restrict__ W_out, const float* __restrict__ b_out,
    const int* __restrict__ st, const float* __restrict__ aux,
    const float* __restrict__ tgt_seq, const float* __restrict__ v,
    float* __restrict__ outp, int t)
{
    extern __shared__ float sh[];
    float* w1 = sh;            // [1024]: W_ih[(2048+j)*13 + 0]  (dec column)
    float* ew = sh + HID;      // j*6: [emb0..emb4 | W_out]
    __shared__ float sloss;
    int tid = threadIdx.x;

    for (int j = tid; j < HID; j += 256) w1[j] = W_ih[(2048 + j) * 13];
    for (int idx = tid; idx < HID * 6; idx += 256) {
        int j = idx / 6, c = idx - j * 6;
        ew[idx] = (c < 5) ? emb[c * HID + j] : W_out[j];
    }
    if (tid == 0) sloss = 0.0f;
    __syncthreads();

    int lane = tid & 31;
    int wid = tid >> 5;
    int row = blockIdx.x * GRU_WARPS + wid;

    const float* gr = g_gates + (size_t)row * H3;
    const float* inx = g_inaux + ((size_t)t * BSZ + row) * HID;
    __nv_bfloat16* Ab = g_Abf + (size_t)row * KB3;
    float* Hrow = g_H + (size_t)row * HID;

    float dec = __bfloat162float(Ab[1024]) + __bfloat162float(Ab[SEC + 1024]);

    float e0 = 0.f, e1 = 0.f, e2 = 0.f, e3 = 0.f, e4 = 0.f, od = 0.f;

#pragma unroll 4
    for (int j = lane; j < HID; j += 32) {
        float r = sigmoid_fast(gr[j]);
        float z = sigmoid_fast(gr[1024 + j]);
        float in_ = fmaf(dec, w1[j], inx[j]);
        float n = tanh_fast(fmaf(r, gr[2048 + j], in_));
        float hp = Hrow[j];
        float h = (1.0f - z) * n + z * hp;
        Hrow[j] = h;
        __nv_bfloat16 hi, lo;
        split_bf(h, hi, lo);
        Ab[j] = hi; Ab[SEC + j] = lo; Ab[2 * SEC + j] = hi;
        const float* e = &ew[j * 6];
        e0 = fmaf(h, e[0], e0);
        e1 = fmaf(h, e[1], e1);
        e2 = fmaf(h, e[2], e2);
        e3 = fmaf(h, e[3], e3);
        e4 = fmaf(h, e[4], e4);
        od = fmaf(h, e[5], od);
    }

    float vals[6] = {e0, e1, e2, e3, e4, od};
#pragma unroll
    for (int s = 16; s > 0; s >>= 1)
#pragma unroll
        for (int vv = 0; vv < 6; vv++)
            vals[vv] += __shfl_down_sync(0xffffffffu, vals[vv], s);

    float o = 0.0f;
    if (lane == 0) {
        float mx = vals[0];
#pragma unroll
        for (int k2 = 1; k2 < 5; k2++) mx = fmaxf(mx, vals[k2]);
        float se = 0.f;
#pragma unroll
        for (int k2 = 0; k2 < 5; k2++) se += __expf(vals[k2] - mx);
        float lse = mx + __logf(se);
        int pos = st[row * TT + t];
        atomicAdd(&sloss, lse - vals[pos]);
        o = vals[5] + b_out[0];
        outp[row * TT + t] = o;
    }
    o = __shfl_sync(0xffffffffu, o, 0);

    // fused x-fill for step t+1
    if (t + 1 < TT && lane < 14) {
        float xv;
        if (lane == 0) {
            float tg = tgt_seq[row * TT + t];
            float m = (tg != 0.0f) ? v[row * TT + t + 1] : 0.0f;
            xv = (m == 1.0f) ? tg : o;
        } else if (lane == 13) {
            xv = 1.0f;
        } else {
            xv = aux[(row * TT + t + 1) * 12 + (lane - 1)];
        }
        __nv_bfloat16 hi, lo;
        split_bf(xv, hi, lo);
        Ab[1024 + lane] = hi;
        Ab[SEC + 1024 + lane] = lo;
        Ab[2 * SEC + 1024 + lane] = hi;
    }

    __syncthreads();
    if (tid == 0) atomicAdd(&g_loss, sloss);
}

// ---------------------------------------------------------------------------
__global__ void k_final(float* outp, int out_size) {
    if (out_size > BSZ * TT)
        outp[BSZ * TT] = g_loss * (1.0f / ((float)BSZ * (float)TT));
}

// ---------------------------------------------------------------------------
extern "C" void kernel_launch(void* const* d_in, const int* in_sizes, int n_in,
                              void* d_out, int out_size) {
    const float* aux    = (const float*)d_in[0];
    const float* cur_pm = (const float*)d_in[1];
    const float* hn     = (const float*)d_in[2];
    const int*   st     = (const int*)  d_in[3];
    const float* tgt    = (const float*)d_in[4];
    const float* v      = (const float*)d_in[5];
    const float* W_ih   = (const float*)d_in[6];
    const float* W_hh   = (const float*)d_in[7];
    const float* b_ih   = (const float*)d_in[8];
    const float* b_hh   = (const float*)d_in[9];
    const float* emb    = (const float*)d_in[10];
    const float* W_out  = (const float*)d_in[11];
    const float* b_out  = (const float*)d_in[12];
    float* outp = (float*)d_out;

    const int gemm_smem  = STAGES * 32768;       // 96 KB -> 2 CTAs/SM
    const int gru_smem   = (HID + HID * 6) * 4;  // 28 KB
    const int inaux_smem = 13 * HID * 4;         // 52 KB
    cudaFuncSetAttribute(k_gru_w, cudaFuncAttributeMaxDynamicSharedMemorySize, gru_smem);
    cudaFuncSetAttribute(k_gemm_mma, cudaFuncAttributeMaxDynamicSharedMemorySize, gemm_smem);
    cudaFuncSetAttribute(k_inaux, cudaFuncAttributeMaxDynamicSharedMemorySize, inaux_smem);

    k_init<<<BSZ, 256>>>(hn, cur_pm, aux);
    k_wbf<<<2048, 256>>>(W_hh, W_ih, b_ih, b_hh);
    {
        dim3 gi(TT, BSZ / 64);
        k_inaux<<<gi, 256, inaux_smem>>>(aux, W_ih, b_ih);
    }

    dim3 gg(H3 / 128, BSZ / 128);
    for (int t = 0; t < TT; t++) {
        k_gemm_mma<<<gg, 128, gemm_smem>>>();
        k_gru_w<<<BSZ / GRU_WARPS, 256, gru_smem>>>(W_ih, emb, W_out, b_out, st,
                                                    aux, tgt, v, outp, t);
    }
    k_final<<<1, 1>>>(outp, out_size);
}

// round 14
// speedup vs baseline: 1.4397x; 1.3300x over previous
#include <cuda_runtime.h>
#include <cuda_fp16.h>
#include <cstdint>
#include <math.h>

#define BSZ 4096
#define TT  24
#define HID 1024
#define H3  3072
#define SEC 1040          // one K-section: 1024 h + 1 dec + 12 aux + 1 bias + 2 pad
#define KB2 2112          // 2*SEC = 2080 padded to multiple of 64
#define CHUNKS 33         // KB2 / 64
#define STAGES 3
#define GRU_WARPS 8

// ---------------- device globals (no cudaMalloc anywhere) ----------------
__device__ __half g_Ah[(size_t)BSZ * KB2];   // [A_hi | A_lo] per row (fp16)
__device__ __half g_Wh[(size_t)H3 * KB2];    // [W_hi | W_hi] per row (fp16)
__device__ float g_gates[(size_t)BSZ * H3];  // GEMM out: [r | z | h_n]
__device__ float g_H[(size_t)BSZ * HID];     // fp32 hidden state
__device__ float g_inaux[(size_t)TT * BSZ * HID];  // aux-part of i_n, all steps
__device__ float g_loss;

__device__ __forceinline__ float tanh_fast(float x) {
    float y;
    asm("tanh.approx.f32 %0, %1;" : "=f"(y) : "f"(x));
    return y;
}
__device__ __forceinline__ float sigmoid_fast(float x) {
    return 0.5f * tanh_fast(0.5f * x) + 0.5f;
}

__device__ __forceinline__ void split_h(float x, __half& hi, __half& lo) {
    hi = __float2half(x);
    lo = __float2half(x - __half2float(hi));
}

// ---------------- PTX helpers (compute_100-safe only) ----------------
__device__ __forceinline__ uint32_t smem_u32(const void* p) {
    uint32_t a;
    asm("{ .reg .u64 t; cvta.to.shared.u64 t, %1; cvt.u32.u64 %0, t; }" : "=r"(a) : "l"(p));
    return a;
}
__device__ __forceinline__ void cp_async16(uint32_t dst, const void* src) {
    asm volatile("cp.async.cg.shared.global [%0], [%1], 16;\n" :: "r"(dst), "l"(src));
}
__device__ __forceinline__ void cp_commit() { asm volatile("cp.async.commit_group;\n"); }
template <int N> __device__ __forceinline__ void cp_waitg() {
    asm volatile("cp.async.wait_group %0;\n" :: "n"(N));
}
__device__ __forceinline__ void ldm_x4(uint32_t& r0, uint32_t& r1, uint32_t& r2, uint32_t& r3,
                                       uint32_t addr) {
    asm volatile("ldmatrix.sync.aligned.m8n8.x4.shared.b16 {%0,%1,%2,%3}, [%4];"
                 : "=r"(r0), "=r"(r1), "=r"(r2), "=r"(r3) : "r"(addr));
}
__device__ __forceinline__ void mma_f16(float& c0, float& c1, float& c2, float& c3,
                                        uint32_t a0, uint32_t a1, uint32_t a2, uint32_t a3,
                                        uint32_t b0, uint32_t b1) {
    asm volatile("mma.sync.aligned.m16n8k16.row.col.f32.f16.f16.f32 "
                 "{%0,%1,%2,%3}, {%4,%5,%6,%7}, {%8,%9}, {%0,%1,%2,%3};"
                 : "+f"(c0), "+f"(c1), "+f"(c2), "+f"(c3)
                 : "r"(a0), "r"(a1), "r"(a2), "r"(a3), "r"(b0), "r"(b1));
}
__device__ __forceinline__ uint32_t sw128(uint32_t bo) { return bo ^ ((bo >> 3) & 0x70); }

// ---------------------------------------------------------------------------
// Init: A" <- split(hn), g_H <- hn, pads <- 0, t=0 x-columns, loss <- 0
// ---------------------------------------------------------------------------
__global__ void k_init(const float* __restrict__ hn, const float* __restrict__ cur_pm,
                       const float* __restrict__ aux) {
    int row = blockIdx.x;
    int tid = threadIdx.x;
    __half* Ab = g_Ah + (size_t)row * KB2;
    for (int j = tid; j < HID; j += blockDim.x) {
        float x = hn[row * HID + j];
        __half hi, lo;
        split_h(x, hi, lo);
        Ab[j] = hi; Ab[SEC + j] = lo;
        g_H[row * HID + j] = x;
    }
    if (tid < 32) Ab[2080 + tid] = __float2half(0.0f);
    if (tid < 14) {
        float xv = (tid == 0) ? cur_pm[row]
                 : (tid == 13) ? 1.0f
                 : aux[(row * TT + 0) * 12 + (tid - 1)];
        __half hi, lo;
        split_h(xv, hi, lo);
        Ab[1024 + tid] = hi;
        Ab[SEC + 1024 + tid] = lo;
    }
    if (tid == 0) {
        __half z = __float2half(0.0f);
        for (int s = 0; s < 2; s++) { Ab[s * SEC + 1038] = z; Ab[s * SEC + 1039] = z; }
        if (row == 0) g_loss = 0.0f;
    }
}

// ---------------------------------------------------------------------------
// Build W" fp16 [3072 x 2112]: sections [W_hi | W_hi] (duplicate)
// ---------------------------------------------------------------------------
__global__ void k_wbf(const float* __restrict__ W_hh, const float* __restrict__ W_ih,
                      const float* __restrict__ b_ih, const float* __restrict__ b_hh) {
    size_t total = (size_t)H3 * KB2;
    for (size_t idx = (size_t)blockIdx.x * blockDim.x + threadIdx.x; idx < total;
         idx += (size_t)gridDim.x * blockDim.x) {
        int c = (int)(idx / KB2);
        int k = (int)(idx - (size_t)c * KB2);
        __half outv;
        if (k >= 2080) {
            outv = __float2half(0.0f);
        } else {
            int sec = (k >= SEC) ? 1 : 0;
            int kk = k - sec * SEC;
            float val;
            if (kk < 1024) val = W_hh[c * 1024 + kk];
            else if (kk <= 1036) val = (c < 2048) ? W_ih[c * 13 + (kk - 1024)] : 0.0f;
            else if (kk == 1037) val = (c < 2048) ? (b_ih[c] + b_hh[c]) : b_hh[c];
            else val = 0.0f;
            outv = __float2half(val);  // both sections hold W_hi
        }
        g_Wh[idx] = outv;
    }
}

// ---------------------------------------------------------------------------
// Precompute aux-part of i_n for ALL steps (fp32):
//   g_inaux[t][row][j] = b_ih[2048+j] + sum_f aux[row,t,f] * W_ih[(2048+j)*13 + 1 + f]
// ---------------------------------------------------------------------------
__global__ void __launch_bounds__(256) k_inaux(const float* __restrict__ aux,
                                               const float* __restrict__ W_ih,
                                               const float* __restrict__ b_ih) {
    extern __shared__ float wt[];  // wt[c*1024 + j]
    int tid = threadIdx.x;
    for (int idx = tid; idx < 13 * HID; idx += 256) {
        int c = idx >> 10, j = idx & 1023;
        wt[idx] = (c == 0) ? b_ih[2048 + j] : W_ih[(2048 + j) * 13 + c];
    }
    __syncthreads();
    int t = blockIdx.x;
    int lane = tid & 31, wid = tid >> 5;
    for (int rr = 0; rr < 8; rr++) {
        int row = blockIdx.y * 64 + wid * 8 + rr;
        float ax[12];
#pragma unroll
        for (int f = 0; f < 12; f++) ax[f] = aux[(row * TT + t) * 12 + f];
        float* out = g_inaux + ((size_t)t * BSZ + row) * HID;
#pragma unroll 2
        for (int j = lane; j < HID; j += 32) {
            float s = wt[j];
#pragma unroll
            for (int f = 0; f < 12; f++) s = fmaf(ax[f], wt[(f + 1) * HID + j], s);
            out[j] = s;
        }
    }
}

// ---------------------------------------------------------------------------
// Tensor-core GEMM via mma.sync (fp16 operands, fp32 accum):
//   gates[m][n] = sum_k A"[m][k] * W"[n][k],  K = 2112 (33 chunks)
// 128x128 CTA tile, block 128 (4 warps, 2x2 of 64x64 warp tiles), 3-stage
// cp.async pipeline, ONE __syncthreads per chunk, prefetch distance 2,
// kk fragment double-buffering.
// ---------------------------------------------------------------------------
__global__ void __launch_bounds__(128, 2) k_gemm_mma() {
    extern __shared__ char smem[];
    uint32_t sb = smem_u32(smem);
    const int tid = threadIdx.x;      // 0..127
    const int wid = tid >> 5;         // 0..3
    const int lane = tid & 31;
    const int bn = blockIdx.x * 128;  // 24 N-tiles
    const int bm = blockIdx.y * 128;  // 32 M-tiles
    const int wm = wid >> 1;          // 0..1 -> 64-row slab
    const int wn = wid & 1;           // 0..1 -> 64-col slab

    const __half* Ag = g_Ah + (size_t)bm * KB2;
    const __half* Wg = g_Wh + (size_t)bn * KB2;

    float acc[4][8][4];
#pragma unroll
    for (int i = 0; i < 4; i++)
#pragma unroll
        for (int j = 0; j < 8; j++)
#pragma unroll
            for (int v2 = 0; v2 < 4; v2++) acc[i][j][v2] = 0.0f;

    const int rA = (lane & 7) + ((lane >> 3) & 1) * 8;
    const int cA = (lane >> 4) * 16;
    const int rB = lane & 7;
    const int hB = ((lane >> 3) & 1) * 16;
    const int pB = (lane >> 4);

#define FILL(s, c) do {                                                          \
    uint32_t _ab = sb + (uint32_t)(s) * 32768u;                                  \
    uint32_t _bb = _ab + 16384u;                                                 \
    _Pragma("unroll")                                                            \
    for (int q = 0; q < 8; q++) {                                                \
        int i = tid + q * 128;                                                   \
        int row = i >> 3, seg = i & 7;                                           \
        uint32_t bo = (uint32_t)(row * 128 + seg * 16);                          \
        uint32_t sw = sw128(bo);                                                 \
        const char* ga = (const char*)(Ag + (size_t)row * KB2 + (c) * 64) + seg * 16; \
        const char* gb = (const char*)(Wg + (size_t)row * KB2 + (c) * 64) + seg * 16; \
        cp_async16(_ab + sw, ga);                                                \
        cp_async16(_bb + sw, gb);                                                \
    }                                                                            \
} while (0)

    FILL(0, 0); cp_commit();
    FILL(1, 1); cp_commit();

    // stage rotation without %: st3 cycles 0,1,2,0,...
    int st3 = 0;      // stage of current chunk c
    int pf3 = 2;      // stage of prefetch chunk c+2

    for (int c = 0; c < CHUNKS; c++) {
        if (c + 2 < CHUNKS) {
            cp_waitg<1>();
            __syncthreads();
            FILL(pf3, c + 2);
            cp_commit();
        } else if (c + 1 < CHUNKS) {
            cp_waitg<1>();
            __syncthreads();
        } else {
            cp_waitg<0>();
            __syncthreads();
        }

        uint32_t ab = sb + (uint32_t)st3 * 32768u;
        uint32_t bb = ab + 16384u;

        uint32_t af[2][4][4];
        uint32_t bfr[2][8][2];

#define LOADF(buf, kk) do {                                                      \
    _Pragma("unroll")                                                            \
    for (int mt = 0; mt < 4; mt++) {                                             \
        uint32_t bo = (uint32_t)((wm * 64 + mt * 16 + rA) * 128 + (kk) * 32 + cA); \
        ldm_x4(af[buf][mt][0], af[buf][mt][1], af[buf][mt][2], af[buf][mt][3],   \
               ab + sw128(bo));                                                  \
    }                                                                            \
    _Pragma("unroll")                                                            \
    for (int ntp = 0; ntp < 4; ntp++) {                                          \
        uint32_t bo = (uint32_t)((wn * 64 + (ntp * 2 + pB) * 8 + rB) * 128 + (kk) * 32 + hB); \
        ldm_x4(bfr[buf][ntp * 2][0], bfr[buf][ntp * 2][1],                       \
               bfr[buf][ntp * 2 + 1][0], bfr[buf][ntp * 2 + 1][1],               \
               bb + sw128(bo));                                                  \
    }                                                                            \
} while (0)

#define MMAS(buf) do {                                                           \
    _Pragma("unroll")                                                            \
    for (int mt = 0; mt < 4; mt++)                                               \
        _Pragma("unroll")                                                        \
        for (int nt = 0; nt < 8; nt++)                                           \
            mma_f16(acc[mt][nt][0], acc[mt][nt][1], acc[mt][nt][2], acc[mt][nt][3], \
                    af[buf][mt][0], af[buf][mt][1], af[buf][mt][2], af[buf][mt][3], \
                    bfr[buf][nt][0], bfr[buf][nt][1]);                           \
} while (0)

        LOADF(0, 0);
        LOADF(1, 1);
        MMAS(0);
        LOADF(0, 2);
        MMAS(1);
        LOADF(1, 3);
        MMAS(0);
        MMAS(1);

#undef LOADF
#undef MMAS

        st3 = (st3 == 2) ? 0 : st3 + 1;
        pf3 = (pf3 == 2) ? 0 : pf3 + 1;
    }
#undef FILL

    int quad = lane >> 2;
    int tig = lane & 3;
#pragma unroll
    for (int mt = 0; mt < 4; mt++) {
        int row0 = bm + wm * 64 + mt * 16 + quad;
#pragma unroll
        for (int nt = 0; nt < 8; nt++) {
            int col = bn + wn * 64 + nt * 8 + tig * 2;
            *(float2*)&g_gates[(size_t)row0 * H3 + col] =
                make_float2(acc[mt][nt][0], acc[mt][nt][1]);
            *(float2*)&g_gates[(size_t)(row0 + 8) * H3 + col] =
                make_float2(acc[mt][nt][2], acc[mt][nt][3]);
        }
    }
}

// ---------------------------------------------------------------------------
// Warp-per-row GRU elementwise + reductions + fused x-fill for step t+1.
// i_n = g_inaux[t][row] + dec * w1.  smem = w1 (4KB) + ew (24KB) -> 28KB.
// ---------------------------------------------------------------------------
__global__ void __launch_bounds__(256) k_gru_w(
    const float* __restrict__ W_ih, const float* __restrict__ emb,
    const float* __restrict__ W_out, const float* __restrict__ b_out,
    const int* __restrict__ st, const float* __restrict__ aux,
    const float* __restrict__ tgt_seq, const float* __restrict__ v,
    float* __restrict__ outp, int t)
{
    extern __shared__ float sh[];
    float* w1 = sh;            // [1024]: W_ih[(2048+j)*13 + 0]  (dec column)
    float* ew = sh + HID;      // j*6: [emb0..emb4 | W_out]
    __shared__ float sloss;
    int tid = threadIdx.x;

    for (int j = tid; j < HID; j += 256) w1[j] = W_ih[(2048 + j) * 13];
    for (int idx = tid; idx < HID * 6; idx += 256) {
        int j = idx / 6, c = idx - j * 6;
        ew[idx] = (c < 5) ? emb[c * HID + j] : W_out[j];
    }
    if (tid == 0) sloss = 0.0f;
    __syncthreads();

    int lane = tid & 31;
    int wid = tid >> 5;
    int row = blockIdx.x * GRU_WARPS + wid;

    const float* gr = g_gates + (size_t)row * H3;
    const float* inx = g_inaux + ((size_t)t * BSZ + row) * HID;
    __half* Ab = g_Ah + (size_t)row * KB2;
    float* Hrow = g_H + (size_t)row * HID;

    float dec = __half2float(Ab[1024]) + __half2float(Ab[SEC + 1024]);

    float e0 = 0.f, e1 = 0.f, e2 = 0.f, e3 = 0.f, e4 = 0.f, od = 0.f;

#pragma unroll 4
    for (int j = lane; j < HID; j += 32) {
        float r = sigmoid_fast(gr[j]);
        float z = sigmoid_fast(gr[1024 + j]);
        float in_ = fmaf(dec, w1[j], inx[j]);
        float n = tanh_fast(fmaf(r, gr[2048 + j], in_));
        float hp = Hrow[j];
        float h = (1.0f - z) * n + z * hp;
        Hrow[j] = h;
        __half hi, lo;
        split_h(h, hi, lo);
        Ab[j] = hi; Ab[SEC + j] = lo;
        const float* e = &ew[j * 6];
        e0 = fmaf(h, e[0], e0);
        e1 = fmaf(h, e[1], e1);
        e2 = fmaf(h, e[2], e2);
        e3 = fmaf(h, e[3], e3);
        e4 = fmaf(h, e[4], e4);
        od = fmaf(h, e[5], od);
    }

    float vals[6] = {e0, e1, e2, e3, e4, od};
#pragma unroll
    for (int s = 16; s > 0; s >>= 1)
#pragma unroll
        for (int vv = 0; vv < 6; vv++)
            vals[vv] += __shfl_down_sync(0xffffffffu, vals[vv], s);

    float o = 0.0f;
    if (lane == 0) {
        float mx = vals[0];
#pragma unroll
        for (int k2 = 1; k2 < 5; k2++) mx = fmaxf(mx, vals[k2]);
        float se = 0.f;
#pragma unroll
        for (int k2 = 0; k2 < 5; k2++) se += __expf(vals[k2] - mx);
        float lse = mx + __logf(se);
        int pos = st[row * TT + t];
        atomicAdd(&sloss, lse - vals[pos]);
        o = vals[5] + b_out[0];
        outp[row * TT + t] = o;
    }
    o = __shfl_sync(0xffffffffu, o, 0);

    // fused x-fill for step t+1
    if (t + 1 < TT && lane < 14) {
        float xv;
        if (lane == 0) {
            float tg = tgt_seq[row * TT + t];
            float m = (tg != 0.0f) ? v[row * TT + t + 1] : 0.0f;
            xv = (m == 1.0f) ? tg : o;
        } else if (lane == 13) {
            xv = 1.0f;
        } else {
            xv = aux[(row * TT + t + 1) * 12 + (lane - 1)];
        }
        __half hi, lo;
        split_h(xv, hi, lo);
        Ab[1024 + lane] = hi;
        Ab[SEC + 1024 + lane] = lo;
    }

    __syncthreads();
    if (tid == 0) atomicAdd(&g_loss, sloss);
}

// ---------------------------------------------------------------------------
__global__ void k_final(float* outp, int out_size) {
    if (out_size > BSZ * TT)
        outp[BSZ * TT] = g_loss * (1.0f / ((float)BSZ * (float)TT));
}

// ---------------------------------------------------------------------------
extern "C" void kernel_launch(void* const* d_in, const int* in_sizes, int n_in,
                              void* d_out, int out_size) {
    const float* aux    = (const float*)d_in[0];
    const float* cur_pm = (const float*)d_in[1];
    const float* hn     = (const float*)d_in[2];
    const int*   st     = (const int*)  d_in[3];
    const float* tgt    = (const float*)d_in[4];
    const float* v      = (const float*)d_in[5];
    const float* W_ih   = (const float*)d_in[6];
    const float* W_hh   = (const float*)d_in[7];
    const float* b_ih   = (const float*)d_in[8];
    const float* b_hh   = (const float*)d_in[9];
    const float* emb    = (const float*)d_in[10];
    const float* W_out  = (const float*)d_in[11];
    const float* b_out  = (const float*)d_in[12];
    float* outp = (float*)d_out;

    const int gemm_smem  = STAGES * 32768;       // 96 KB -> 2 CTAs/SM
    const int gru_smem   = (HID + HID * 6) * 4;  // 28 KB
    const int inaux_smem = 13 * HID * 4;         // 52 KB
    cudaFuncSetAttribute(k_gru_w, cudaFuncAttributeMaxDynamicSharedMemorySize, gru_smem);
    cudaFuncSetAttribute(k_gemm_mma, cudaFuncAttributeMaxDynamicSharedMemorySize, gemm_smem);
    cudaFuncSetAttribute(k_inaux, cudaFuncAttributeMaxDynamicSharedMemorySize, inaux_smem);

    k_init<<<BSZ, 256>>>(hn, cur_pm, aux);
    k_wbf<<<2048, 256>>>(W_hh, W_ih, b_ih, b_hh);
    {
        dim3 gi(TT, BSZ / 64);
        k_inaux<<<gi, 256, inaux_smem>>>(aux, W_ih, b_ih);
    }

    dim3 gg(H3 / 128, BSZ / 128);
    for (int t = 0; t < TT; t++) {
        k_gemm_mma<<<gg, 128, gemm_smem>>>();
        k_gru_w<<<BSZ / GRU_WARPS, 256, gru_smem>>>(W_ih, emb, W_out, b_out, st,
                                                    aux, tgt, v, outp, t);
    }
    k_final<<<1, 1>>>(outp, out_size);
}

// round 15
// speedup vs baseline: 2.2264x; 1.5465x over previous
#include <cuda_runtime.h>
#include <cuda_fp16.h>
#include <cstdint>
#include <math.h>

#define BSZ 4096
#define TT  24
#define HID 1024
#define H3  3072
#define KBW 1088          // 1024 (h) + 1 dec + 12 aux + 1 bias + pad -> 17*64
#define CHUNKS 17         // KBW / 64
#define STAGES 3
#define GRU_WARPS 8

// ---------------- device globals (no cudaMalloc anywhere) ----------------
__device__ __half g_Ah[(size_t)BSZ * KBW];   // [h | dec | aux | 1 | pad] fp16
__device__ __half g_Wh[(size_t)H3 * KBW];    // combined weights fp16
__device__ float g_gates[(size_t)BSZ * H3];  // GEMM out: [r | z | h_n]
__device__ float g_H[(size_t)BSZ * HID];     // fp32 hidden state
__device__ float g_inaux[(size_t)TT * BSZ * HID];  // aux-part of i_n, all steps
__device__ float g_loss;

__device__ __forceinline__ float tanh_fast(float x) {
    float y;
    asm("tanh.approx.f32 %0, %1;" : "=f"(y) : "f"(x));
    return y;
}
__device__ __forceinline__ float sigmoid_fast(float x) {
    return 0.5f * tanh_fast(0.5f * x) + 0.5f;
}

// ---------------- PTX helpers (compute_100-safe only) ----------------
__device__ __forceinline__ uint32_t smem_u32(const void* p) {
    uint32_t a;
    asm("{ .reg .u64 t; cvta.to.shared.u64 t, %1; cvt.u32.u64 %0, t; }" : "=r"(a) : "l"(p));
    return a;
}
__device__ __forceinline__ void cp_async16(uint32_t dst, const void* src) {
    asm volatile("cp.async.cg.shared.global [%0], [%1], 16;\n" :: "r"(dst), "l"(src));
}
__device__ __forceinline__ void cp_commit() { asm volatile("cp.async.commit_group;\n"); }
template <int N> __device__ __forceinline__ void cp_waitg() {
    asm volatile("cp.async.wait_group %0;\n" :: "n"(N));
}
__device__ __forceinline__ void ldm_x4(uint32_t& r0, uint32_t& r1, uint32_t& r2, uint32_t& r3,
                                       uint32_t addr) {
    asm volatile("ldmatrix.sync.aligned.m8n8.x4.shared.b16 {%0,%1,%2,%3}, [%4];"
                 : "=r"(r0), "=r"(r1), "=r"(r2), "=r"(r3) : "r"(addr));
}
__device__ __forceinline__ void mma_f16(float& c0, float& c1, float& c2, float& c3,
                                        uint32_t a0, uint32_t a1, uint32_t a2, uint32_t a3,
                                        uint32_t b0, uint32_t b1) {
    asm volatile("mma.sync.aligned.m16n8k16.row.col.f32.f16.f16.f32 "
                 "{%0,%1,%2,%3}, {%4,%5,%6,%7}, {%8,%9}, {%0,%1,%2,%3};"
                 : "+f"(c0), "+f"(c1), "+f"(c2), "+f"(c3)
                 : "r"(a0), "r"(a1), "r"(a2), "r"(a3), "r"(b0), "r"(b1));
}
__device__ __forceinline__ uint32_t sw128(uint32_t bo) { return bo ^ ((bo >> 3) & 0x70); }

// ---------------------------------------------------------------------------
// Init: A <- fp16(hn), g_H <- hn, pads <- 0, t=0 x-columns, loss <- 0
// ---------------------------------------------------------------------------
__global__ void k_init(const float* __restrict__ hn, const float* __restrict__ cur_pm,
                       const float* __restrict__ aux) {
    int row = blockIdx.x;
    int tid = threadIdx.x;
    __half* Ab = g_Ah + (size_t)row * KBW;
    for (int j = tid; j < HID; j += blockDim.x) {
        float x = hn[row * HID + j];
        Ab[j] = __float2half(x);
        g_H[row * HID + j] = x;
    }
    if (tid < 50) Ab[1038 + tid] = __float2half(0.0f);  // 1038..1087
    if (tid < 14) {
        float xv = (tid == 0) ? cur_pm[row]
                 : (tid == 13) ? 1.0f
                 : aux[(row * TT + 0) * 12 + (tid - 1)];
        Ab[1024 + tid] = __float2half(xv);
    }
    if (tid == 0 && row == 0) g_loss = 0.0f;
}

// ---------------------------------------------------------------------------
// Build W fp16 [3072 x 1088]
// ---------------------------------------------------------------------------
__global__ void k_wbf(const float* __restrict__ W_hh, const float* __restrict__ W_ih,
                      const float* __restrict__ b_ih, const float* __restrict__ b_hh) {
    size_t total = (size_t)H3 * KBW;
    for (size_t idx = (size_t)blockIdx.x * blockDim.x + threadIdx.x; idx < total;
         idx += (size_t)gridDim.x * blockDim.x) {
        int c = (int)(idx / KBW);
        int kk = (int)(idx - (size_t)c * KBW);
        float val;
        if (kk < 1024) val = W_hh[c * 1024 + kk];
        else if (kk <= 1036) val = (c < 2048) ? W_ih[c * 13 + (kk - 1024)] : 0.0f;
        else if (kk == 1037) val = (c < 2048) ? (b_ih[c] + b_hh[c]) : b_hh[c];
        else val = 0.0f;
        g_Wh[idx] = __float2half(val);
    }
}

// ---------------------------------------------------------------------------
// Precompute aux-part of i_n for ALL steps (fp32):
//   g_inaux[t][row][j] = b_ih[2048+j] + sum_f aux[row,t,f] * W_ih[(2048+j)*13 + 1 + f]
// ---------------------------------------------------------------------------
__global__ void __launch_bounds__(256) k_inaux(const float* __restrict__ aux,
                                               const float* __restrict__ W_ih,
                                               const float* __restrict__ b_ih) {
    extern __shared__ float wt[];  // wt[c*1024 + j]
    int tid = threadIdx.x;
    for (int idx = tid; idx < 13 * HID; idx += 256) {
        int c = idx >> 10, j = idx & 1023;
        wt[idx] = (c == 0) ? b_ih[2048 + j] : W_ih[(2048 + j) * 13 + c];
    }
    __syncthreads();
    int t = blockIdx.x;
    int lane = tid & 31, wid = tid >> 5;
    for (int rr = 0; rr < 8; rr++) {
        int row = blockIdx.y * 64 + wid * 8 + rr;
        float ax[12];
#pragma unroll
        for (int f = 0; f < 12; f++) ax[f] = aux[(row * TT + t) * 12 + f];
        float* out = g_inaux + ((size_t)t * BSZ + row) * HID;
#pragma unroll 2
        for (int j = lane; j < HID; j += 32) {
            float s = wt[j];
#pragma unroll
            for (int f = 0; f < 12; f++) s = fmaf(ax[f], wt[(f + 1) * HID + j], s);
            out[j] = s;
        }
    }
}

// ---------------------------------------------------------------------------
// Tensor-core GEMM via mma.sync (fp16 operands, fp32 accum):
//   gates[m][n] = sum_k A[m][k] * W[n][k],  K = 1088 (17 chunks)
// 128x128 CTA tile, block 128 (4 warps, 2x2 of 64x64 warp tiles), 3-stage
// cp.async pipeline, ONE __syncthreads per chunk, prefetch distance 2,
// kk fragment double-buffering.
// ---------------------------------------------------------------------------
__global__ void __launch_bounds__(128, 2) k_gemm_mma() {
    extern __shared__ char smem[];
    uint32_t sb = smem_u32(smem);
    const int tid = threadIdx.x;      // 0..127
    const int wid = tid >> 5;         // 0..3
    const int lane = tid & 31;
    const int bn = blockIdx.x * 128;  // 24 N-tiles
    const int bm = blockIdx.y * 128;  // 32 M-tiles
    const int wm = wid >> 1;          // 0..1 -> 64-row slab
    const int wn = wid & 1;           // 0..1 -> 64-col slab

    const __half* Ag = g_Ah + (size_t)bm * KBW;
    const __half* Wg = g_Wh + (size_t)bn * KBW;

    float acc[4][8][4];
#pragma unroll
    for (int i = 0; i < 4; i++)
#pragma unroll
        for (int j = 0; j < 8; j++)
#pragma unroll
            for (int v2 = 0; v2 < 4; v2++) acc[i][j][v2] = 0.0f;

    const int rA = (lane & 7) + ((lane >> 3) & 1) * 8;
    const int cA = (lane >> 4) * 16;
    const int rB = lane & 7;
    const int hB = ((lane >> 3) & 1) * 16;
    const int pB = (lane >> 4);

#define FILL(s, c) do {                                                          \
    uint32_t _ab = sb + (uint32_t)(s) * 32768u;                                  \
    uint32_t _bb = _ab + 16384u;                                                 \
    _Pragma("unroll")                                                            \
    for (int q = 0; q < 8; q++) {                                                \
        int i = tid + q * 128;                                                   \
        int row = i >> 3, seg = i & 7;                                           \
        uint32_t bo = (uint32_t)(row * 128 + seg * 16);                          \
        uint32_t sw = sw128(bo);                                                 \
        const char* ga = (const char*)(Ag + (size_t)row * KBW + (c) * 64) + seg * 16; \
        const char* gb = (const char*)(Wg + (size_t)row * KBW + (c) * 64) + seg * 16; \
        cp_async16(_ab + sw, ga);                                                \
        cp_async16(_bb + sw, gb);                                                \
    }                                                                            \
} while (0)

    FILL(0, 0); cp_commit();
    FILL(1, 1); cp_commit();

    // stage rotation without %: st3 cycles 0,1,2,0,...
    int st3 = 0;      // stage of current chunk c
    int pf3 = 2;      // stage of prefetch chunk c+2

    for (int c = 0; c < CHUNKS; c++) {
        if (c + 2 < CHUNKS) {
            cp_waitg<1>();
            __syncthreads();
            FILL(pf3, c + 2);
            cp_commit();
        } else if (c + 1 < CHUNKS) {
            cp_waitg<1>();
            __syncthreads();
        } else {
            cp_waitg<0>();
            __syncthreads();
        }

        uint32_t ab = sb + (uint32_t)st3 * 32768u;
        uint32_t bb = ab + 16384u;

        uint32_t af[2][4][4];
        uint32_t bfr[2][8][2];

#define LOADF(buf, kk) do {                                                      \
    _Pragma("unroll")                                                            \
    for (int mt = 0; mt < 4; mt++) {                                             \
        uint32_t bo = (uint32_t)((wm * 64 + mt * 16 + rA) * 128 + (kk) * 32 + cA); \
        ldm_x4(af[buf][mt][0], af[buf][mt][1], af[buf][mt][2], af[buf][mt][3],   \
               ab + sw128(bo));                                                  \
    }                                                                            \
    _Pragma("unroll")                                                            \
    for (int ntp = 0; ntp < 4; ntp++) {                                          \
        uint32_t bo = (uint32_t)((wn * 64 + (ntp * 2 + pB) * 8 + rB) * 128 + (kk) * 32 + hB); \
        ldm_x4(bfr[buf][ntp * 2][0], bfr[buf][ntp * 2][1],                       \
               bfr[buf][ntp * 2 + 1][0], bfr[buf][ntp * 2 + 1][1],               \
               bb + sw128(bo));                                                  \
    }                                                                            \
} while (0)

#define MMAS(buf) do {                                                           \
    _Pragma("unroll")                                                            \
    for (int mt = 0; mt < 4; mt++)                                               \
        _Pragma("unroll")                                                        \
        for (int nt = 0; nt < 8; nt++)                                           \
            mma_f16(acc[mt][nt][0], acc[mt][nt][1], acc[mt][nt][2], acc[mt][nt][3], \
                    af[buf][mt][0], af[buf][mt][1], af[buf][mt][2], af[buf][mt][3], \
                    bfr[buf][nt][0], bfr[buf][nt][1]);                           \
} while (0)

        LOADF(0, 0);
        LOADF(1, 1);
        MMAS(0);
        LOADF(0, 2);
        MMAS(1);
        LOADF(1, 3);
        MMAS(0);
        MMAS(1);

#undef LOADF
#undef MMAS

        st3 = (st3 == 2) ? 0 : st3 + 1;
        pf3 = (pf3 == 2) ? 0 : pf3 + 1;
    }
#undef FILL

    int quad = lane >> 2;
    int tig = lane & 3;
#pragma unroll
    for (int mt = 0; mt < 4; mt++) {
        int row0 = bm + wm * 64 + mt * 16 + quad;
#pragma unroll
        for (int nt = 0; nt < 8; nt++) {
            int col = bn + wn * 64 + nt * 8 + tig * 2;
            *(float2*)&g_gates[(size_t)row0 * H3 + col] =
                make_float2(acc[mt][nt][0], acc[mt][nt][1]);
            *(float2*)&g_gates[(size_t)(row0 + 8) * H3 + col] =
                make_float2(acc[mt][nt][2], acc[mt][nt][3]);
        }
    }
}

// ---------------------------------------------------------------------------
// Warp-per-row GRU elementwise + reductions + fused x-fill for step t+1.
// i_n = g_inaux[t][row] + dec * w1.  smem = w1 (4KB) + ew (24KB) -> 28KB.
// ---------------------------------------------------------------------------
__global__ void __launch_bounds__(256) k_gru_w(
    const float* __restrict__ W_ih, const float* __restrict__ emb,
    const float* __restrict__ W_out, const float* __restrict__ b_out,
    const int* __restrict__ st, const float* __restrict__ aux,
    const float* __restrict__ tgt_seq, const float* __restrict__ v,
    float* __restrict__ outp, int t)
{
    extern __shared__ float sh[];
    float* w1 = sh;            // [1024]: W_ih[(2048+j)*13 + 0]  (dec column)
    float* ew = sh + HID;      // j*6: [emb0..emb4 | W_out]
    __shared__ float sloss;
    int tid = threadIdx.x;

    for (int j = tid; j < HID; j += 256) w1[j] = W_ih[(2048 + j) * 13];
    for (int idx = tid; idx < HID * 6; idx += 256) {
        int j = idx / 6, c = idx - j * 6;
        ew[idx] = (c < 5) ? emb[c * HID + j] : W_out[j];
    }
    if (tid == 0) sloss = 0.0f;
    __syncthreads();

    int lane = tid & 31;
    int wid = tid >> 5;
    int row = blockIdx.x * GRU_WARPS + wid;

    const float* gr = g_gates + (size_t)row * H3;
    const float* inx = g_inaux + ((size_t)t * BSZ + row) * HID;
    __half* Ab = g_Ah + (size_t)row * KBW;
    float* Hrow = g_H + (size_t)row * HID;

    float dec = __half2float(Ab[1024]);

    float e0 = 0.f, e1 = 0.f, e2 = 0.f, e3 = 0.f, e4 = 0.f, od = 0.f;

#pragma unroll 4
    for (int j = lane; j < HID; j += 32) {
        float r = sigmoid_fast(gr[j]);
        float z = sigmoid_fast(gr[1024 + j]);
        float in_ = fmaf(dec, w1[j], inx[j]);
        float n = tanh_fast(fmaf(r, gr[2048 + j], in_));
        float hp = Hrow[j];
        float h = (1.0f - z) * n + z * hp;
        Hrow[j] = h;
        Ab[j] = __float2half(h);
        const float* e = &ew[j * 6];
        e0 = fmaf(h, e[0], e0);
        e1 = fmaf(h, e[1], e1);
        e2 = fmaf(h, e[2], e2);
        e3 = fmaf(h, e[3], e3);
        e4 = fmaf(h, e[4], e4);
        od = fmaf(h, e[5], od);
    }

    float vals[6] = {e0, e1, e2, e3, e4, od};
#pragma unroll
    for (int s = 16; s > 0; s >>= 1)
#pragma unroll
        for (int vv = 0; vv < 6; vv++)
            vals[vv] += __shfl_down_sync(0xffffffffu, vals[vv], s);

    float o = 0.0f;
    if (lane == 0) {
        float mx = vals[0];
#pragma unroll
        for (int k2 = 1; k2 < 5; k2++) mx = fmaxf(mx, vals[k2]);
        float se = 0.f;
#pragma unroll
        for (int k2 = 0; k2 < 5; k2++) se += __expf(vals[k2] - mx);
        float lse = mx + __logf(se);
        int pos = st[row * TT + t];
        atomicAdd(&sloss, lse - vals[pos]);
        o = vals[5] + b_out[0];
        outp[row * TT + t] = o;
    }
    o = __shfl_sync(0xffffffffu, o, 0);

    // fused x-fill for step t+1
    if (t + 1 < TT && lane < 14) {
        float xv;
        if (lane == 0) {
            float tg = tgt_seq[row * TT + t];
            float m = (tg != 0.0f) ? v[row * TT + t + 1] : 0.0f;
            xv = (m == 1.0f) ? tg : o;
        } else if (lane == 13) {
            xv = 1.0f;
        } else {
            xv = aux[(row * TT + t + 1) * 12 + (lane - 1)];
        }
        Ab[1024 + lane] = __float2half(xv);
    }

    __syncthreads();
    if (tid == 0) atomicAdd(&g_loss, sloss);
}

// ---------------------------------------------------------------------------
__global__ void k_final(float* outp, int out_size) {
    if (out_size > BSZ * TT)
        outp[BSZ * TT] = g_loss * (1.0f / ((float)BSZ * (float)TT));
}

// ---------------------------------------------------------------------------
extern "C" void kernel_launch(void* const* d_in, const int* in_sizes, int n_in,
                              void* d_out, int out_size) {
    const float* aux    = (const float*)d_in[0];
    const float* cur_pm = (const float*)d_in[1];
    const float* hn     = (const float*)d_in[2];
    const int*   st     = (const int*)  d_in[3];
    const float* tgt    = (const float*)d_in[4];
    const float* v      = (const float*)d_in[5];
    const float* W_ih   = (const float*)d_in[6];
    const float* W_hh   = (const float*)d_in[7];
    const float* b_ih   = (const float*)d_in[8];
    const float* b_hh   = (const float*)d_in[9];
    const float* emb    = (const float*)d_in[10];
    const float* W_out  = (const float*)d_in[11];
    const float* b_out  = (const float*)d_in[12];
    float* outp = (float*)d_out;

    const int gemm_smem  = STAGES * 32768;       // 96 KB -> 2 CTAs/SM
    const int gru_smem   = (HID + HID * 6) * 4;  // 28 KB
    const int inaux_smem = 13 * HID * 4;         // 52 KB
    cudaFuncSetAttribute(k_gru_w, cudaFuncAttributeMaxDynamicSharedMemorySize, gru_smem);
    cudaFuncSetAttribute(k_gemm_mma, cudaFuncAttributeMaxDynamicSharedMemorySize, gemm_smem);
    cudaFuncSetAttribute(k_inaux, cudaFuncAttributeMaxDynamicSharedMemorySize, inaux_smem);

    k_init<<<BSZ, 256>>>(hn, cur_pm, aux);
    k_wbf<<<2048, 256>>>(W_hh, W_ih, b_ih, b_hh);
    {
        dim3 gi(TT, BSZ / 64);
        k_inaux<<<gi, 256, inaux_smem>>>(aux, W_ih, b_ih);
    }

    dim3 gg(H3 / 128, BSZ / 128);
    for (int t = 0; t < TT; t++) {
        k_gemm_mma<<<gg, 128, gemm_smem>>>();
        k_gru_w<<<BSZ / GRU_WARPS, 256, gru_smem>>>(W_ih, emb, W_out, b_out, st,
                                                    aux, tgt, v, outp, t);
    }
    k_final<<<1, 1>>>(outp, out_size);
}

// round 16
// speedup vs baseline: 2.4864x; 1.1168x over previous
#include <cuda_runtime.h>
#include <cuda_fp16.h>
#include <cstdint>
#include <math.h>

#define BSZ 4096
#define TT  24
#define HID 1024
#define H3  3072
#define KBW 1088          // 1024 (h) + 1 dec + 12 aux + 1 bias + pad -> 17*64
#define CHUNKS 17         // KBW / 64
#define STAGES 3
#define GRU_WARPS 8

// ---------------- device globals (no cudaMalloc anywhere) ----------------
__device__ __half g_Ah[(size_t)BSZ * KBW];   // [h | dec | aux | 1 | pad] fp16
__device__ __half g_Wh[(size_t)H3 * KBW];    // combined weights fp16
__device__ __half g_gates[(size_t)BSZ * H3]; // GEMM out: [r | z | h_n] fp16
__device__ float g_H[(size_t)BSZ * HID];     // fp32 hidden state
__device__ __half g_inaux[(size_t)TT * BSZ * HID];  // aux-part of i_n, all steps
__device__ float g_loss;

__device__ __forceinline__ float tanh_fast(float x) {
    float y;
    asm("tanh.approx.f32 %0, %1;" : "=f"(y) : "f"(x));
    return y;
}
__device__ __forceinline__ float sigmoid_fast(float x) {
    return 0.5f * tanh_fast(0.5f * x) + 0.5f;
}

// ---------------- PTX helpers (compute_100-safe only) ----------------
__device__ __forceinline__ uint32_t smem_u32(const void* p) {
    uint32_t a;
    asm("{ .reg .u64 t; cvta.to.shared.u64 t, %1; cvt.u32.u64 %0, t; }" : "=r"(a) : "l"(p));
    return a;
}
__device__ __forceinline__ void cp_async16(uint32_t dst, const void* src) {
    asm volatile("cp.async.cg.shared.global [%0], [%1], 16;\n" :: "r"(dst), "l"(src));
}
__device__ __forceinline__ void cp_commit() { asm volatile("cp.async.commit_group;\n"); }
template <int N> __device__ __forceinline__ void cp_waitg() {
    asm volatile("cp.async.wait_group %0;\n" :: "n"(N));
}
__device__ __forceinline__ void ldm_x4(uint32_t& r0, uint32_t& r1, uint32_t& r2, uint32_t& r3,
                                       uint32_t addr) {
    asm volatile("ldmatrix.sync.aligned.m8n8.x4.shared.b16 {%0,%1,%2,%3}, [%4];"
                 : "=r"(r0), "=r"(r1), "=r"(r2), "=r"(r3) : "r"(addr));
}
__device__ __forceinline__ void mma_f16(float& c0, float& c1, float& c2, float& c3,
                                        uint32_t a0, uint32_t a1, uint32_t a2, uint32_t a3,
                                        uint32_t b0, uint32_t b1) {
    asm volatile("mma.sync.aligned.m16n8k16.row.col.f32.f16.f16.f32 "
                 "{%0,%1,%2,%3}, {%4,%5,%6,%7}, {%8,%9}, {%0,%1,%2,%3};"
                 : "+f"(c0), "+f"(c1), "+f"(c2), "+f"(c3)
                 : "r"(a0), "r"(a1), "r"(a2), "r"(a3), "r"(b0), "r"(b1));
}
__device__ __forceinline__ uint32_t sw128(uint32_t bo) { return bo ^ ((bo >> 3) & 0x70); }

// ---------------------------------------------------------------------------
// Init: A <- fp16(hn), g_H <- hn, pads <- 0, t=0 x-columns, loss <- 0
// ---------------------------------------------------------------------------
__global__ void k_init(const float* __restrict__ hn, const float* __restrict__ cur_pm,
                       const float* __restrict__ aux) {
    int row = blockIdx.x;
    int tid = threadIdx.x;
    __half* Ab = g_Ah + (size_t)row * KBW;
    for (int j = tid; j < HID; j += blockDim.x) {
        float x = hn[row * HID + j];
        Ab[j] = __float2half(x);
        g_H[row * HID + j] = x;
    }
    if (tid < 50) Ab[1038 + tid] = __float2half(0.0f);  // 1038..1087
    if (tid < 14) {
        float xv = (tid == 0) ? cur_pm[row]
                 : (tid == 13) ? 1.0f
                 : aux[(row * TT + 0) * 12 + (tid - 1)];
        Ab[1024 + tid] = __float2half(xv);
    }
    if (tid == 0 && row == 0) g_loss = 0.0f;
}

// ---------------------------------------------------------------------------
// Build W fp16 [3072 x 1088]
// ---------------------------------------------------------------------------
__global__ void k_wbf(const float* __restrict__ W_hh, const float* __restrict__ W_ih,
                      const float* __restrict__ b_ih, const float* __restrict__ b_hh) {
    size_t total = (size_t)H3 * KBW;
    for (size_t idx = (size_t)blockIdx.x * blockDim.x + threadIdx.x; idx < total;
         idx += (size_t)gridDim.x * blockDim.x) {
        int c = (int)(idx / KBW);
        int kk = (int)(idx - (size_t)c * KBW);
        float val;
        if (kk < 1024) val = W_hh[c * 1024 + kk];
        else if (kk <= 1036) val = (c < 2048) ? W_ih[c * 13 + (kk - 1024)] : 0.0f;
        else if (kk == 1037) val = (c < 2048) ? (b_ih[c] + b_hh[c]) : b_hh[c];
        else val = 0.0f;
        g_Wh[idx] = __float2half(val);
    }
}

// ---------------------------------------------------------------------------
// Precompute aux-part of i_n for ALL steps (fp16 out):
//   g_inaux[t][row][j] = b_ih[2048+j] + sum_f aux[row,t,f] * W_ih[(2048+j)*13 + 1 + f]
// ---------------------------------------------------------------------------
__global__ void __launch_bounds__(256) k_inaux(const float* __restrict__ aux,
                                               const float* __restrict__ W_ih,
                                               const float* __restrict__ b_ih) {
    extern __shared__ float wt[];  // wt[c*1024 + j]
    int tid = threadIdx.x;
    for (int idx = tid; idx < 13 * HID; idx += 256) {
        int c = idx >> 10, j = idx & 1023;
        wt[idx] = (c == 0) ? b_ih[2048 + j] : W_ih[(2048 + j) * 13 + c];
    }
    __syncthreads();
    int t = blockIdx.x;
    int lane = tid & 31, wid = tid >> 5;
    for (int rr = 0; rr < 8; rr++) {
        int row = blockIdx.y * 64 + wid * 8 + rr;
        float ax[12];
#pragma unroll
        for (int f = 0; f < 12; f++) ax[f] = aux[(row * TT + t) * 12 + f];
        __half* out = g_inaux + ((size_t)t * BSZ + row) * HID;
#pragma unroll 2
        for (int j = lane; j < HID; j += 32) {
            float s = wt[j];
#pragma unroll
            for (int f = 0; f < 12; f++) s = fmaf(ax[f], wt[(f + 1) * HID + j], s);
            out[j] = __float2half(s);
        }
    }
}

// ---------------------------------------------------------------------------
// Tensor-core GEMM via mma.sync (fp16 operands, fp32 accum, fp16 output):
//   gates[m][n] = sum_k A[m][k] * W[n][k],  K = 1088 (17 chunks)
// 128x128 CTA tile, block 128 (4 warps, 2x2 of 64x64 warp tiles), 3-stage
// cp.async pipeline, ONE __syncthreads per chunk, prefetch distance 2,
// kk fragment double-buffering. Epilogue packs half2 (halved write traffic).
// ---------------------------------------------------------------------------
__global__ void __launch_bounds__(128, 2) k_gemm_mma() {
    extern __shared__ char smem[];
    uint32_t sb = smem_u32(smem);
    const int tid = threadIdx.x;      // 0..127
    const int wid = tid >> 5;         // 0..3
    const int lane = tid & 31;
    const int bn = blockIdx.x * 128;  // 24 N-tiles
    const int bm = blockIdx.y * 128;  // 32 M-tiles
    const int wm = wid >> 1;          // 0..1 -> 64-row slab
    const int wn = wid & 1;           // 0..1 -> 64-col slab

    const __half* Ag = g_Ah + (size_t)bm * KBW;
    const __half* Wg = g_Wh + (size_t)bn * KBW;

    float acc[4][8][4];
#pragma unroll
    for (int i = 0; i < 4; i++)
#pragma unroll
        for (int j = 0; j < 8; j++)
#pragma unroll
            for (int v2 = 0; v2 < 4; v2++) acc[i][j][v2] = 0.0f;

    const int rA = (lane & 7) + ((lane >> 3) & 1) * 8;
    const int cA = (lane >> 4) * 16;
    const int rB = lane & 7;
    const int hB = ((lane >> 3) & 1) * 16;
    const int pB = (lane >> 4);

#define FILL(s, c) do {                                                          \
    uint32_t _ab = sb + (uint32_t)(s) * 32768u;                                  \
    uint32_t _bb = _ab + 16384u;                                                 \
    _Pragma("unroll")                                                            \
    for (int q = 0; q < 8; q++) {                                                \
        int i = tid + q * 128;                                                   \
        int row = i >> 3, seg = i & 7;                                           \
        uint32_t bo = (uint32_t)(row * 128 + seg * 16);                          \
        uint32_t sw = sw128(bo);                                                 \
        const char* ga = (const char*)(Ag + (size_t)row * KBW + (c) * 64) + seg * 16; \
        const char* gb = (const char*)(Wg + (size_t)row * KBW + (c) * 64) + seg * 16; \
        cp_async16(_ab + sw, ga);                                                \
        cp_async16(_bb + sw, gb);                                                \
    }                                                                            \
} while (0)

    FILL(0, 0); cp_commit();
    FILL(1, 1); cp_commit();

    // stage rotation without %: st3 cycles 0,1,2,0,...
    int st3 = 0;      // stage of current chunk c
    int pf3 = 2;      // stage of prefetch chunk c+2

    for (int c = 0; c < CHUNKS; c++) {
        if (c + 2 < CHUNKS) {
            cp_waitg<1>();
            __syncthreads();
            FILL(pf3, c + 2);
            cp_commit();
        } else if (c + 1 < CHUNKS) {
            cp_waitg<1>();
            __syncthreads();
        } else {
            cp_waitg<0>();
            __syncthreads();
        }

        uint32_t ab = sb + (uint32_t)st3 * 32768u;
        uint32_t bb = ab + 16384u;

        uint32_t af[2][4][4];
        uint32_t bfr[2][8][2];

#define LOADF(buf, kk) do {                                                      \
    _Pragma("unroll")                                                            \
    for (int mt = 0; mt < 4; mt++) {                                             \
        uint32_t bo = (uint32_t)((wm * 64 + mt * 16 + rA) * 128 + (kk) * 32 + cA); \
        ldm_x4(af[buf][mt][0], af[buf][mt][1], af[buf][mt][2], af[buf][mt][3],   \
               ab + sw128(bo));                                                  \
    }                                                                            \
    _Pragma("unroll")                                                            \
    for (int ntp = 0; ntp < 4; ntp++) {                                          \
        uint32_t bo = (uint32_t)((wn * 64 + (ntp * 2 + pB) * 8 + rB) * 128 + (kk) * 32 + hB); \
        ldm_x4(bfr[buf][ntp * 2][0], bfr[buf][ntp * 2][1],                       \
               bfr[buf][ntp * 2 + 1][0], bfr[buf][ntp * 2 + 1][1],               \
               bb + sw128(bo));                                                  \
    }                                                                            \
} while (0)

#define MMAS(buf) do {                                                           \
    _Pragma("unroll")                                                            \
    for (int mt = 0; mt < 4; mt++)                                               \
        _Pragma("unroll")                                                        \
        for (int nt = 0; nt < 8; nt++)                                           \
            mma_f16(acc[mt][nt][0], acc[mt][nt][1], acc[mt][nt][2], acc[mt][nt][3], \
                    af[buf][mt][0], af[buf][mt][1], af[buf][mt][2], af[buf][mt][3], \
                    bfr[buf][nt][0], bfr[buf][nt][1]);                           \
} while (0)

        LOADF(0, 0);
        LOADF(1, 1);
        MMAS(0);
        LOADF(0, 2);
        MMAS(1);
        LOADF(1, 3);
        MMAS(0);
        MMAS(1);

#undef LOADF
#undef MMAS

        st3 = (st3 == 2) ? 0 : st3 + 1;
        pf3 = (pf3 == 2) ? 0 : pf3 + 1;
    }
#undef FILL

    int quad = lane >> 2;
    int tig = lane & 3;
#pragma unroll
    for (int mt = 0; mt < 4; mt++) {
        int row0 = bm + wm * 64 + mt * 16 + quad;
#pragma unroll
        for (int nt = 0; nt < 8; nt++) {
            int col = bn + wn * 64 + nt * 8 + tig * 2;
            *(__half2*)&g_gates[(size_t)row0 * H3 + col] =
                __floats2half2_rn(acc[mt][nt][0], acc[mt][nt][1]);
            *(__half2*)&g_gates[(size_t)(row0 + 8) * H3 + col] =
                __floats2half2_rn(acc[mt][nt][2], acc[mt][nt][3]);
        }
    }
}

// ---------------------------------------------------------------------------
// Warp-per-row GRU elementwise + reductions + fused x-fill for step t+1.
// i_n = g_inaux[t][row] + dec * w1.  smem = w1 (4KB) + ew (24KB) -> 28KB.
// ---------------------------------------------------------------------------
__global__ void __launch_bounds__(256) k_gru_w(
    const float* __restrict__ W_ih, const float* __restrict__ emb,
    const float* __restrict__ W_out, const float* __restrict__ b_out,
    const int* __restrict__ st, const float* __restrict__ aux,
    const float* __restrict__ tgt_seq, const float* __restrict__ v,
    float* __restrict__ outp, int t)
{
    extern __shared__ float sh[];
    float* w1 = sh;            // [1024]: W_ih[(2048+j)*13 + 0]  (dec column)
    float* ew = sh + HID;      // j*6: [emb0..emb4 | W_out]
    __shared__ float sloss;
    int tid = threadIdx.x;

    for (int j = tid; j < HID; j += 256) w1[j] = W_ih[(2048 + j) * 13];
    for (int idx = tid; idx < HID * 6; idx += 256) {
        int j = idx / 6, c = idx - j * 6;
        ew[idx] = (c < 5) ? emb[c * HID + j] : W_out[j];
    }
    if (tid == 0) sloss = 0.0f;
    __syncthreads();

    int lane = tid & 31;
    int wid = tid >> 5;
    int row = blockIdx.x * GRU_WARPS + wid;

    const __half* gr = g_gates + (size_t)row * H3;
    const __half* inx = g_inaux + ((size_t)t * BSZ + row) * HID;
    __half* Ab = g_Ah + (size_t)row * KBW;
    float* Hrow = g_H + (size_t)row * HID;

    float dec = __half2float(Ab[1024]);

    float e0 = 0.f, e1 = 0.f, e2 = 0.f, e3 = 0.f, e4 = 0.f, od = 0.f;

#pragma unroll 4
    for (int j = lane; j < HID; j += 32) {
        float r = sigmoid_fast(__half2float(gr[j]));
        float z = sigmoid_fast(__half2float(gr[1024 + j]));
        float in_ = fmaf(dec, w1[j], __half2float(inx[j]));
        float n = tanh_fast(fmaf(r, __half2float(gr[2048 + j]), in_));
        float hp = Hrow[j];
        float h = (1.0f - z) * n + z * hp;
        Hrow[j] = h;
        Ab[j] = __float2half(h);
        const float* e = &ew[j * 6];
        e0 = fmaf(h, e[0], e0);
        e1 = fmaf(h, e[1], e1);
        e2 = fmaf(h, e[2], e2);
        e3 = fmaf(h, e[3], e3);
        e4 = fmaf(h, e[4], e4);
        od = fmaf(h, e[5], od);
    }

    float vals[6] = {e0, e1, e2, e3, e4, od};
#pragma unroll
    for (int s = 16; s > 0; s >>= 1)
#pragma unroll
        for (int vv = 0; vv < 6; vv++)
            vals[vv] += __shfl_down_sync(0xffffffffu, vals[vv], s);

    float o = 0.0f;
    if (lane == 0) {
        float mx = vals[0];
#pragma unroll
        for (int k2 = 1; k2 < 5; k2++) mx = fmaxf(mx, vals[k2]);
        float se = 0.f;
#pragma unroll
        for (int k2 = 0; k2 < 5; k2++) se += __expf(vals[k2] - mx);
        float lse = mx + __logf(se);
        int pos = st[row * TT + t];
        atomicAdd(&sloss, lse - vals[pos]);
        o = vals[5] + b_out[0];
        outp[row * TT + t] = o;
    }
    o = __shfl_sync(0xffffffffu, o, 0);

    // fused x-fill for step t+1
    if (t + 1 < TT && lane < 14) {
        float xv;
        if (lane == 0) {
            float tg = tgt_seq[row * TT + t];
            float m = (tg != 0.0f) ? v[row * TT + t + 1] : 0.0f;
            xv = (m == 1.0f) ? tg : o;
        } else if (lane == 13) {
            xv = 1.0f;
        } else {
            xv = aux[(row * TT + t + 1) * 12 + (lane - 1)];
        }
        Ab[1024 + lane] = __float2half(xv);
    }

    __syncthreads();
    if (tid == 0) atomicAdd(&g_loss, sloss);
}

// ---------------------------------------------------------------------------
__global__ void k_final(float* outp, int out_size) {
    if (out_size > BSZ * TT)
        outp[BSZ * TT] = g_loss * (1.0f / ((float)BSZ * (float)TT));
}

// ---------------------------------------------------------------------------
extern "C" void kernel_launch(void* const* d_in, const int* in_sizes, int n_in,
                              void* d_out, int out_size) {
    const float* aux    = (const float*)d_in[0];
    const float* cur_pm = (const float*)d_in[1];
    const float* hn     = (const float*)d_in[2];
    const int*   st     = (const int*)  d_in[3];
    const float* tgt    = (const float*)d_in[4];
    const float* v      = (const float*)d_in[5];
    const float* W_ih   = (const float*)d_in[6];
    const float* W_hh   = (const float*)d_in[7];
    const float* b_ih   = (const float*)d_in[8];
    const float* b_hh   = (const float*)d_in[9];
    const float* emb    = (const float*)d_in[10];
    const float* W_out  = (const float*)d_in[11];
    const float* b_out  = (const float*)d_in[12];
    float* outp = (float*)d_out;

    const int gemm_smem  = STAGES * 32768;       // 96 KB -> 2 CTAs/SM
    const int gru_smem   = (HID + HID * 6) * 4;  // 28 KB
    const int inaux_smem = 13 * HID * 4;         // 52 KB
    cudaFuncSetAttribute(k_gru_w, cudaFuncAttributeMaxDynamicSharedMemorySize, gru_smem);
    cudaFuncSetAttribute(k_gemm_mma, cudaFuncAttributeMaxDynamicSharedMemorySize, gemm_smem);
    cudaFuncSetAttribute(k_inaux, cudaFuncAttributeMaxDynamicSharedMemorySize, inaux_smem);

    k_init<<<BSZ, 256>>>(hn, cur_pm, aux);
    k_wbf<<<2048, 256>>>(W_hh, W_ih, b_ih, b_hh);
    {
        dim3 gi(TT, BSZ / 64);
        k_inaux<<<gi, 256, inaux_smem>>>(aux, W_ih, b_ih);
    }

    dim3 gg(H3 / 128, BSZ / 128);
    for (int t = 0; t < TT; t++) {
        k_gemm_mma<<<gg, 128, gemm_smem>>>();
        k_gru_w<<<BSZ / GRU_WARPS, 256, gru_smem>>>(W_ih, emb, W_out, b_out, st,
                                                    aux, tgt, v, outp, t);
    }
    k_final<<<1, 1>>>(outp, out_size);
}